// round 8
// baseline (speedup 1.0000x reference)
#include <cuda_runtime.h>
#include <math.h>
#include <stdint.h>

// Problem constants
#define NNODE 8192
#define NEDGE 131072
#define NTOT  (NNODE + NEDGE)   // 139264
#define HDIM  128
#define H3    384
#define MDIM  64

typedef unsigned long long ull;

// ---------------- device scratch (static globals: allowed) ----------------
__device__ float g_x  [(size_t)NTOT * HDIM];
__device__ float g_m  [(size_t)NTOT * HDIM];   // reused as hm1
__device__ float g_agg[(size_t)NTOT * HDIM];   // reused as hm2
__device__ float g_gi [(size_t)NTOT * H3];     // reused as msgs
__device__ float g_gh [(size_t)NTOT * H3];
__device__ float g_nm [NNODE * MDIM];

__device__ int g_deg_var[NNODE], g_off_var[NNODE + 1], g_cur_var[NNODE];
__device__ int g_lst_var[2 * NEDGE];
__device__ int g_deg_row[NNODE], g_off_row[NNODE + 1], g_cur_row[NNODE];
__device__ int g_lst_row[NEDGE];

// ---------------- small helper kernels ----------------
__global__ void zero_deg_kernel(int* degv, int* degr) {
    int i = blockIdx.x * blockDim.x + threadIdx.x;
    if (i < NNODE) { degv[i] = 0; degr[i] = 0; }
}

__global__ void count_kernel(const int* __restrict__ row, const int* __restrict__ col,
                             int* degv, int* degr) {
    int e = blockIdx.x * blockDim.x + threadIdx.x;
    if (e < NEDGE) {
        atomicAdd(&degv[row[e]], 1);
        atomicAdd(&degv[col[e]], 1);
        atomicAdd(&degr[row[e]], 1);
    }
}

// exclusive scan of 8192 ints with one 1024-thread block (8 per thread)
__global__ void scan_kernel(const int* __restrict__ deg, int* __restrict__ off) {
    __shared__ int sm[1024];
    int t = threadIdx.x;
    int v[8], pre[8];
    int s = 0;
#pragma unroll
    for (int i = 0; i < 8; i++) {
        v[i] = deg[t * 8 + i];
        pre[i] = s;
        s += v[i];
    }
    sm[t] = s;
    __syncthreads();
    for (int d = 1; d < 1024; d <<= 1) {
        int add = 0;
        if (t >= d) add = sm[t - d];
        __syncthreads();
        sm[t] += add;
        __syncthreads();
    }
    int base = (t == 0) ? 0 : sm[t - 1];
#pragma unroll
    for (int i = 0; i < 8; i++) off[t * 8 + i] = base + pre[i];
    if (t == 1023) off[8192] = sm[1023];
}

__global__ void copy_cur_kernel(const int* offv, int* curv, const int* offr, int* curr) {
    int i = blockIdx.x * blockDim.x + threadIdx.x;
    if (i < NNODE) { curv[i] = offv[i]; curr[i] = offr[i]; }
}

__global__ void scatter_kernel(const int* __restrict__ row, const int* __restrict__ col,
                               int* curv, int* lstv, int* curr, int* lstr) {
    int e = blockIdx.x * blockDim.x + threadIdx.x;
    if (e < NEDGE) {
        int r = row[e], c = col[e];
        int p = atomicAdd(&curv[r], 1); lstv[p] = e;
        int q = atomicAdd(&curv[c], 1); lstv[q] = e;
        int u = atomicAdd(&curr[r], 1); lstr[u] = e;
    }
}

__global__ void init_x_kernel(float* __restrict__ x, const float* __restrict__ jvals) {
    int idx = blockIdx.x * blockDim.x + threadIdx.x;
    int n = idx >> 7, h = idx & 127;
    float v = 0.0f;
    if (n >= NNODE) {
        if (h == 0) v = 1.0f;
        else if (h == 1) v = jvals[n - NNODE];
    }
    x[(size_t)idx] = v;
}

// agg for factor rows: agg[NNODE+e] = m[row[e]] + m[col[e]]
__global__ void factor_agg_kernel(const float* __restrict__ m,
                                  const int* __restrict__ row, const int* __restrict__ col,
                                  float* __restrict__ agg) {
    int t = blockIdx.x * blockDim.x + threadIdx.x;
    int e = t >> 5, q = t & 31;
    const float4* m4 = (const float4*)m;
    float4* a4 = (float4*)agg;
    int r = row[e], c = col[e];
    float4 a = m4[(size_t)r * 32 + q];
    float4 b = m4[(size_t)c * 32 + q];
    a4[(size_t)(NNODE + e) * 32 + q] = make_float4(a.x + b.x, a.y + b.y, a.z + b.z, a.w + b.w);
}

// agg for variable rows: sum over incident factor messages (CSR)
__global__ void var_agg_kernel(const float* __restrict__ m,
                               const int* __restrict__ off, const int* __restrict__ lst,
                               float* __restrict__ agg) {
    int v = blockIdx.x;
    int h = threadIdx.x;
    int s = off[v], e = off[v + 1];
    float acc = 0.0f;
    for (int p = s; p < e; p++) {
        int ed = lst[p];
        acc += m[(size_t)(NNODE + ed) * HDIM + h];
    }
    agg[(size_t)v * HDIM + h] = acc;
}

// node_msgs: segment_sum(msgs, row) over n_nodes (CSR of row only)
__global__ void node_msgs_kernel(const float* __restrict__ msgs,
                                 const int* __restrict__ off, const int* __restrict__ lst,
                                 float* __restrict__ nm) {
    int v = blockIdx.x;
    int h = threadIdx.x;   // 64
    int s = off[v], e = off[v + 1];
    float acc = 0.0f;
    for (int p = s; p < e; p++) {
        int ed = lst[p];
        acc += msgs[(size_t)ed * MDIM + h];
    }
    nm[v * MDIM + h] = acc;
}

// fused GRU elementwise update (biases already added in GEMM epilogue)
__global__ void gru_kernel(const float* __restrict__ gi, const float* __restrict__ gh,
                           float* __restrict__ x) {
    int idx = blockIdx.x * blockDim.x + threadIdx.x;
    int n = idx >> 7, h = idx & 127;
    size_t b = (size_t)n * H3;
    float ir = gi[b + h],        hr = gh[b + h];
    float iz = gi[b + HDIM + h], hz = gh[b + HDIM + h];
    float in_ = gi[b + 2 * HDIM + h], hn = gh[b + 2 * HDIM + h];
    float r = 1.0f / (1.0f + expf(-(ir + hr)));
    float z = 1.0f / (1.0f + expf(-(iz + hz)));
    float nn = tanhf(in_ + r * hn);
    x[(size_t)idx] = (1.0f - z) * nn + z * x[(size_t)idx];
}

// ---------------- packed-f32x2 SGEMM ----------------
// C[M,N] = A[M,K] * B (+bias, optional relu), using fma.rn.f32x2 (FFMA2).
// BM=128, BN=128, BK=16, 256 threads (16x16), micro-tile 8Mx8N.
// Accumulators packed along M (pairs of consecutive rows).
// B is duplicated in SMEM so the replicated operand comes straight from LDS.128.
// bT = 0: B is K x N row-major (ldb = N).  bT = 1: B is N x K row-major (ldb = K).
// Requires M%128==0, N%128==0, K%16==0.

__device__ __forceinline__ void ffma2(ull& acc, ull a, ull b) {
    asm("fma.rn.f32x2 %0, %1, %2, %0;" : "+l"(acc) : "l"(a), "l"(b));
}
__device__ __forceinline__ void unpack2(float& lo, float& hi, ull v) {
    asm("mov.b64 {%0, %1}, %2;" : "=f"(lo), "=f"(hi) : "l"(v));
}

// position of (k, n) inside the duplicated/reordered Bs tile.
// Read pattern: per kk, thread tx issues 4 LDS.128 at kk*256 + sub*64 + tx*4,
// each delivering pairs {b_{2sub} dup, b_{2sub+1} dup} for its 8 columns.
__device__ __forceinline__ int bpos(int k, int n) {
    int tx = n >> 3, j = n & 7;
    return k * 256 + (j >> 1) * 64 + tx * 4 + (j & 1) * 2;
}

__global__ void __launch_bounds__(256, 2)
sgemm2_kernel(const float* __restrict__ A, const float* __restrict__ B,
              const float* __restrict__ bias, float* __restrict__ C,
              int M, int N, int K, int ldb, int bT, int doRelu) {
    __shared__ float As[16 * 128];   // [k][m]
    __shared__ float Bs[16 * 256];   // duplicated + reordered, see bpos()
    int tid = threadIdx.x;
    int bn = blockIdx.x * 128;
    int bm = blockIdx.y * 128;
    int tx = tid & 15;   // n micro (8 cols)
    int ty = tid >> 4;   // m micro (8 rows = 4 pairs)

    ull acc[4][8];
#pragma unroll
    for (int i = 0; i < 4; i++)
#pragma unroll
        for (int j = 0; j < 8; j++) acc[i][j] = 0ull;

    int kq = tid & 3;          // A/B-TN load: k quad
    int lr = tid >> 2;         // A/B-TN load: row 0..63
    int n4 = tid & 31;         // B-NN load: n float4 group
    int kb = tid >> 5;         // B-NN load: k 0..7

    for (int kt = 0; kt < K; kt += 16) {
        // ---- load A tile 128x16 into As[k][m] (coalesced 64B runs) ----
#pragma unroll
        for (int p = 0; p < 2; p++) {
            int r = lr + p * 64;
            float4 v = *(const float4*)&A[(size_t)(bm + r) * K + kt + kq * 4];
            As[(kq * 4 + 0) * 128 + r] = v.x;
            As[(kq * 4 + 1) * 128 + r] = v.y;
            As[(kq * 4 + 2) * 128 + r] = v.z;
            As[(kq * 4 + 3) * 128 + r] = v.w;
        }
        // ---- load B tile 16x128, duplicated ----
        if (bT) {
#pragma unroll
            for (int p = 0; p < 2; p++) {
                int n = lr + p * 64;
                float4 v = *(const float4*)&B[(size_t)(bn + n) * ldb + kt + kq * 4];
                float vv[4] = {v.x, v.y, v.z, v.w};
#pragma unroll
                for (int c = 0; c < 4; c++) {
                    int pp = bpos(kq * 4 + c, n);
                    Bs[pp] = vv[c]; Bs[pp + 1] = vv[c];
                }
            }
        } else {
#pragma unroll
            for (int p = 0; p < 2; p++) {
                int k = kb + p * 8;
                float4 v = *(const float4*)&B[(size_t)(kt + k) * ldb + bn + n4 * 4];
                float vv[4] = {v.x, v.y, v.z, v.w};
#pragma unroll
                for (int c = 0; c < 4; c++) {
                    int pp = bpos(k, n4 * 4 + c);
                    Bs[pp] = vv[c]; Bs[pp + 1] = vv[c];
                }
            }
        }
        __syncthreads();

#pragma unroll
        for (int kk = 0; kk < 16; kk++) {
            // a: 4 M-pairs (rows ty*8 .. ty*8+7), two LDS.128
            ulonglong2 aA = *(const ulonglong2*)&As[kk * 128 + ty * 8];
            ulonglong2 aB = *(const ulonglong2*)&As[kk * 128 + ty * 8 + 4];
            ull a2[4] = {aA.x, aA.y, aB.x, aB.y};
            // b: 8 replicated values, four LDS.128 (conflict-free layout)
            ull b2[8];
#pragma unroll
            for (int sub = 0; sub < 4; sub++) {
                ulonglong2 bv = *(const ulonglong2*)&Bs[kk * 256 + sub * 64 + tx * 4];
                b2[2 * sub]     = bv.x;
                b2[2 * sub + 1] = bv.y;
            }
#pragma unroll
            for (int i = 0; i < 4; i++)
#pragma unroll
                for (int j = 0; j < 8; j++)
                    ffma2(acc[i][j], a2[i], b2[j]);
        }
        __syncthreads();
    }

    // ---- epilogue ----
    float bb[8];
    if (bias) {
        float4 c0 = *(const float4*)&bias[bn + tx * 8];
        float4 c1 = *(const float4*)&bias[bn + tx * 8 + 4];
        bb[0] = c0.x; bb[1] = c0.y; bb[2] = c0.z; bb[3] = c0.w;
        bb[4] = c1.x; bb[5] = c1.y; bb[6] = c1.z; bb[7] = c1.w;
    } else {
#pragma unroll
        for (int j = 0; j < 8; j++) bb[j] = 0.0f;
    }
#pragma unroll
    for (int i = 0; i < 4; i++) {
        float lo[8], hi[8];
#pragma unroll
        for (int j = 0; j < 8; j++) {
            unpack2(lo[j], hi[j], acc[i][j]);
            lo[j] += bb[j]; hi[j] += bb[j];
            if (doRelu) { lo[j] = fmaxf(lo[j], 0.f); hi[j] = fmaxf(hi[j], 0.f); }
        }
        size_t r0 = (size_t)(bm + ty * 8 + 2 * i) * N + bn + tx * 8;
        size_t r1 = r0 + N;
        *(float4*)&C[r0]     = make_float4(lo[0], lo[1], lo[2], lo[3]);
        *(float4*)&C[r0 + 4] = make_float4(lo[4], lo[5], lo[6], lo[7]);
        *(float4*)&C[r1]     = make_float4(hi[0], hi[1], hi[2], hi[3]);
        *(float4*)&C[r1 + 4] = make_float4(hi[4], hi[5], hi[6], hi[7]);
    }
}

// ---------------- scalar tiled SGEMM (kept for N=64 GEMM) ----------------
__global__ void sgemm_kernel(const float* __restrict__ A, const float* __restrict__ B,
                             const float* __restrict__ bias, float* __restrict__ C,
                             int M, int N, int K, int ldb, int bT, int doRelu) {
    __shared__ float As[16 * 128];   // [k][m]
    __shared__ float Bs[16 * 64];    // [k][n]
    int tid = threadIdx.x;
    int bn = blockIdx.x * 64;
    int bm = blockIdx.y * 128;
    int tx = tid & 15;   // n micro
    int ty = tid >> 4;   // m micro
    int arow = tid & 63, acg = tid >> 6;      // A load mapping
    float acc[8][4];
#pragma unroll
    for (int i = 0; i < 8; i++)
#pragma unroll
        for (int j = 0; j < 4; j++) acc[i][j] = 0.0f;

    for (int kt = 0; kt < K; kt += 16) {
#pragma unroll
        for (int p = 0; p < 2; p++) {
            int r = arow + p * 64;
            float4 v = *(const float4*)&A[(size_t)(bm + r) * K + kt + acg * 4];
            As[(acg * 4 + 0) * 128 + r] = v.x;
            As[(acg * 4 + 1) * 128 + r] = v.y;
            As[(acg * 4 + 2) * 128 + r] = v.z;
            As[(acg * 4 + 3) * 128 + r] = v.w;
        }
        if (bT) {
            int n = tid & 63, kg = tid >> 6;
            float4 v = *(const float4*)&B[(size_t)(bn + n) * ldb + kt + kg * 4];
            Bs[(kg * 4 + 0) * 64 + n] = v.x;
            Bs[(kg * 4 + 1) * 64 + n] = v.y;
            Bs[(kg * 4 + 2) * 64 + n] = v.z;
            Bs[(kg * 4 + 3) * 64 + n] = v.w;
        } else {
            int nn = tid & 15, k = tid >> 4;
            float4 v = *(const float4*)&B[(size_t)(kt + k) * ldb + bn + nn * 4];
            *(float4*)&Bs[k * 64 + nn * 4] = v;
        }
        __syncthreads();
#pragma unroll
        for (int kk = 0; kk < 16; kk++) {
            float4 b4 = *(const float4*)&Bs[kk * 64 + tx * 4];
            float4 a0 = *(const float4*)&As[kk * 128 + ty * 8];
            float4 a1 = *(const float4*)&As[kk * 128 + ty * 8 + 4];
            float ar[8] = {a0.x, a0.y, a0.z, a0.w, a1.x, a1.y, a1.z, a1.w};
#pragma unroll
            for (int i = 0; i < 8; i++) {
                acc[i][0] += ar[i] * b4.x;
                acc[i][1] += ar[i] * b4.y;
                acc[i][2] += ar[i] * b4.z;
                acc[i][3] += ar[i] * b4.w;
            }
        }
        __syncthreads();
    }

    float4 bb = make_float4(0.f, 0.f, 0.f, 0.f);
    if (bias) bb = *(const float4*)&bias[bn + tx * 4];
#pragma unroll
    for (int i = 0; i < 8; i++) {
        float4 o;
        o.x = acc[i][0] + bb.x;
        o.y = acc[i][1] + bb.y;
        o.z = acc[i][2] + bb.z;
        o.w = acc[i][3] + bb.w;
        if (doRelu) {
            o.x = fmaxf(o.x, 0.f); o.y = fmaxf(o.y, 0.f);
            o.z = fmaxf(o.z, 0.f); o.w = fmaxf(o.w, 0.f);
        }
        *(float4*)&C[(size_t)(bm + ty * 8 + i) * N + bn + tx * 4] = o;
    }
}

// ---------------- fused readout: 2 dense layers + logits + softmax ----------------
#define NPB 16
__global__ void readout_kernel(const float* __restrict__ nm,
                               const float* __restrict__ W1, const float* __restrict__ b1,
                               const float* __restrict__ W2, const float* __restrict__ b2,
                               const float* __restrict__ W3, const float* __restrict__ b3,
                               float* __restrict__ out) {
    __shared__ float nms[64], h1s[128], h2s[128], red[128];
    __shared__ float l0sh;
    int t = threadIdx.x;   // 128
    int v0 = blockIdx.x * NPB;
    for (int v = v0; v < v0 + NPB; v++) {
        if (t < 64) nms[t] = nm[v * MDIM + t];
        __syncthreads();
        float a = b1[t];
#pragma unroll 4
        for (int k = 0; k < 64; k++) a += nms[k] * W1[k * 128 + t];
        h1s[t] = fmaxf(a, 0.f);
        __syncthreads();
        float c = b2[t];
#pragma unroll 4
        for (int k = 0; k < 128; k++) c += h1s[k] * W2[k * 128 + t];
        h2s[t] = fmaxf(c, 0.f);
        __syncthreads();
        red[t] = h2s[t] * W3[2 * t + 0];
        __syncthreads();
        for (int s = 64; s > 0; s >>= 1) {
            if (t < s) red[t] += red[t + s];
            __syncthreads();
        }
        if (t == 0) l0sh = red[0] + b3[0];
        __syncthreads();
        red[t] = h2s[t] * W3[2 * t + 1];
        __syncthreads();
        for (int s = 64; s > 0; s >>= 1) {
            if (t < s) red[t] += red[t + s];
            __syncthreads();
        }
        if (t == 0) {
            float l0 = l0sh;
            float l1 = red[0] + b3[1];
            float mx = fmaxf(l0, l1);
            float e0 = expf(l0 - mx), e1 = expf(l1 - mx);
            float s_ = e0 + e1;
            out[v * 2 + 0] = e0 / s_;
            out[v * 2 + 1] = e1 / s_;
        }
        __syncthreads();
    }
}

// ---------------- launch ----------------
extern "C" void kernel_launch(void* const* d_in, const int* in_sizes, int n_in,
                              void* d_out, int out_size) {
    const float* jvals = (const float*)d_in[0];
    // d_in[1] = b (unused: only defines n_nodes)
    const int* row = (const int*)d_in[2];
    const int* col = (const int*)d_in[3];
    const float* convW  = (const float*)d_in[4];
    const float* gru_wi = (const float*)d_in[5];
    const float* gru_wh = (const float*)d_in[6];
    const float* gru_bi = (const float*)d_in[7];
    const float* gru_bh = (const float*)d_in[8];
    const float* mp_W1 = (const float*)d_in[9];
    const float* mp_b1 = (const float*)d_in[10];
    const float* mp_W2 = (const float*)d_in[11];
    const float* mp_b2 = (const float*)d_in[12];
    const float* mp_W3 = (const float*)d_in[13];
    const float* mp_b3 = (const float*)d_in[14];
    const float* ro_W1 = (const float*)d_in[15];
    const float* ro_b1 = (const float*)d_in[16];
    const float* ro_W2 = (const float*)d_in[17];
    const float* ro_b2 = (const float*)d_in[18];
    const float* ro_W3 = (const float*)d_in[19];
    const float* ro_b3 = (const float*)d_in[20];
    float* out = (float*)d_out;

    float *x, *m, *agg, *gi, *gh, *nm;
    int *degv, *offv, *curv, *lstv, *degr, *offr, *curr, *lstr;
    cudaGetSymbolAddress((void**)&x,   g_x);
    cudaGetSymbolAddress((void**)&m,   g_m);
    cudaGetSymbolAddress((void**)&agg, g_agg);
    cudaGetSymbolAddress((void**)&gi,  g_gi);
    cudaGetSymbolAddress((void**)&gh,  g_gh);
    cudaGetSymbolAddress((void**)&nm,  g_nm);
    cudaGetSymbolAddress((void**)&degv, g_deg_var);
    cudaGetSymbolAddress((void**)&offv, g_off_var);
    cudaGetSymbolAddress((void**)&curv, g_cur_var);
    cudaGetSymbolAddress((void**)&lstv, g_lst_var);
    cudaGetSymbolAddress((void**)&degr, g_deg_row);
    cudaGetSymbolAddress((void**)&offr, g_off_row);
    cudaGetSymbolAddress((void**)&curr, g_cur_row);
    cudaGetSymbolAddress((void**)&lstr, g_lst_row);

    // ---- CSR build ----
    zero_deg_kernel<<<NNODE / 256, 256>>>(degv, degr);
    count_kernel<<<NEDGE / 256, 256>>>(row, col, degv, degr);
    scan_kernel<<<1, 1024>>>(degv, offv);
    scan_kernel<<<1, 1024>>>(degr, offr);
    copy_cur_kernel<<<NNODE / 256, 256>>>(offv, curv, offr, curr);
    scatter_kernel<<<NEDGE / 256, 256>>>(row, col, curv, lstv, curr, lstr);

    // ---- init x ----
    init_x_kernel<<<(NTOT * HDIM) / 256, 256>>>(x, jvals);

    // ---- 2 GGNN layers ----
    for (int l = 0; l < 2; l++) {
        // m = x @ conv_W[l]            (NN layout)
        sgemm2_kernel<<<dim3(HDIM / 128, NTOT / 128), 256>>>(
            x, convW + (size_t)l * HDIM * HDIM, nullptr, m, NTOT, HDIM, HDIM, HDIM, 0, 0);
        // agg = segment_sum(m[src], dst)
        factor_agg_kernel<<<(NEDGE * 32) / 128, 128>>>(m, row, col, agg);
        var_agg_kernel<<<NNODE, 128>>>(m, offv, lstv, agg);
        // gi = agg @ wi^T + bi, gh = x @ wh^T + bh  (TN layout)
        sgemm2_kernel<<<dim3(H3 / 128, NTOT / 128), 256>>>(
            agg, gru_wi, gru_bi, gi, NTOT, H3, HDIM, HDIM, 1, 0);
        sgemm2_kernel<<<dim3(H3 / 128, NTOT / 128), 256>>>(
            x, gru_wh, gru_bh, gh, NTOT, H3, HDIM, HDIM, 1, 0);
        gru_kernel<<<(NTOT * HDIM) / 256, 256>>>(gi, gh, x);
    }

    // ---- edge MLP on factor rows ----
    const float* xf = x + (size_t)NNODE * HDIM;
    sgemm2_kernel<<<dim3(HDIM / 128, NEDGE / 128), 256>>>(
        xf, mp_W1, mp_b1, m, NEDGE, HDIM, HDIM, HDIM, 0, 1);
    sgemm2_kernel<<<dim3(HDIM / 128, NEDGE / 128), 256>>>(
        m, mp_W2, mp_b2, agg, NEDGE, HDIM, HDIM, HDIM, 0, 1);
    sgemm_kernel<<<dim3(MDIM / 64, NEDGE / 128), 256>>>(
        agg, mp_W3, mp_b3, gi, NEDGE, MDIM, HDIM, MDIM, 0, 0);

    // ---- node_msgs = segment_sum(msgs, row) ----
    node_msgs_kernel<<<NNODE, 64>>>(gi, offr, lstr, nm);

    // ---- readout + softmax ----
    readout_kernel<<<NNODE / NPB, 128>>>(nm, ro_W1, ro_b1, ro_W2, ro_b2, ro_W3, ro_b3, out);
}

// round 12
// speedup vs baseline: 2.1385x; 2.1385x over previous
#include <cuda_runtime.h>
#include <cuda_bf16.h>
#include <math.h>
#include <stdint.h>

// Problem constants
#define NNODE 8192
#define NEDGE 131072
#define NTOT  (NNODE + NEDGE)   // 139264
#define HDIM  128
#define H3    384
#define MDIM  64

// ---------------- device scratch (static globals: allowed) ----------------
__device__ float g_x  [(size_t)NTOT * HDIM];
__device__ float g_m  [(size_t)NTOT * HDIM];   // reused as hm1
__device__ float g_agg[(size_t)NTOT * HDIM];   // reused as hm2
__device__ float g_gi [(size_t)NTOT * H3];     // reused as msgs
__device__ float g_gh [(size_t)NTOT * H3];
__device__ float g_nm [NNODE * MDIM];
// transposed (N-major) weights: conv0, conv1, mp1, mp2, mp3
__device__ float g_wt [4 * 128 * 128 + 64 * 128];

__device__ int g_deg_var[NNODE], g_off_var[NNODE + 1], g_cur_var[NNODE];
__device__ int g_lst_var[2 * NEDGE];
__device__ int g_deg_row[NNODE], g_off_row[NNODE + 1], g_cur_row[NNODE];
__device__ int g_lst_row[NEDGE];

// ---------------- small helper kernels ----------------
__global__ void zero_deg_kernel(int* degv, int* degr) {
    int i = blockIdx.x * blockDim.x + threadIdx.x;
    if (i < NNODE) { degv[i] = 0; degr[i] = 0; }
}

__global__ void count_kernel(const int* __restrict__ row, const int* __restrict__ col,
                             int* degv, int* degr) {
    int e = blockIdx.x * blockDim.x + threadIdx.x;
    if (e < NEDGE) {
        atomicAdd(&degv[row[e]], 1);
        atomicAdd(&degv[col[e]], 1);
        atomicAdd(&degr[row[e]], 1);
    }
}

// exclusive scan of 8192 ints with one 1024-thread block (8 per thread)
__global__ void scan_kernel(const int* __restrict__ deg, int* __restrict__ off) {
    __shared__ int sm[1024];
    int t = threadIdx.x;
    int v[8], pre[8];
    int s = 0;
#pragma unroll
    for (int i = 0; i < 8; i++) {
        v[i] = deg[t * 8 + i];
        pre[i] = s;
        s += v[i];
    }
    sm[t] = s;
    __syncthreads();
    for (int d = 1; d < 1024; d <<= 1) {
        int add = 0;
        if (t >= d) add = sm[t - d];
        __syncthreads();
        sm[t] += add;
        __syncthreads();
    }
    int base = (t == 0) ? 0 : sm[t - 1];
#pragma unroll
    for (int i = 0; i < 8; i++) off[t * 8 + i] = base + pre[i];
    if (t == 1023) off[8192] = sm[1023];
}

__global__ void copy_cur_kernel(const int* offv, int* curv, const int* offr, int* curr) {
    int i = blockIdx.x * blockDim.x + threadIdx.x;
    if (i < NNODE) { curv[i] = offv[i]; curr[i] = offr[i]; }
}

__global__ void scatter_kernel(const int* __restrict__ row, const int* __restrict__ col,
                               int* curv, int* lstv, int* curr, int* lstr) {
    int e = blockIdx.x * blockDim.x + threadIdx.x;
    if (e < NEDGE) {
        int r = row[e], c = col[e];
        int p = atomicAdd(&curv[r], 1); lstv[p] = e;
        int q = atomicAdd(&curv[c], 1); lstv[q] = e;
        int u = atomicAdd(&curr[r], 1); lstr[u] = e;
    }
}

__global__ void init_x_kernel(float* __restrict__ x, const float* __restrict__ jvals) {
    int idx = blockIdx.x * blockDim.x + threadIdx.x;
    int n = idx >> 7, h = idx & 127;
    float v = 0.0f;
    if (n >= NNODE) {
        if (h == 0) v = 1.0f;
        else if (h == 1) v = jvals[n - NNODE];
    }
    x[(size_t)idx] = v;
}

// transpose: in is K x N row-major -> out is N x K row-major
__global__ void transpose_kernel(const float* __restrict__ in, float* __restrict__ out,
                                 int K, int N) {
    int idx = blockIdx.x * blockDim.x + threadIdx.x;
    if (idx < K * N) {
        int k = idx / N, n = idx % N;
        out[n * K + k] = in[idx];
    }
}

// agg for factor rows: agg[NNODE+e] = m[row[e]] + m[col[e]]
__global__ void factor_agg_kernel(const float* __restrict__ m,
                                  const int* __restrict__ row, const int* __restrict__ col,
                                  float* __restrict__ agg) {
    int t = blockIdx.x * blockDim.x + threadIdx.x;
    int e = t >> 5, q = t & 31;
    const float4* m4 = (const float4*)m;
    float4* a4 = (float4*)agg;
    int r = row[e], c = col[e];
    float4 a = m4[(size_t)r * 32 + q];
    float4 b = m4[(size_t)c * 32 + q];
    a4[(size_t)(NNODE + e) * 32 + q] = make_float4(a.x + b.x, a.y + b.y, a.z + b.z, a.w + b.w);
}

// agg for variable rows: sum over incident factor messages (CSR)
__global__ void var_agg_kernel(const float* __restrict__ m,
                               const int* __restrict__ off, const int* __restrict__ lst,
                               float* __restrict__ agg) {
    int v = blockIdx.x;
    int h = threadIdx.x;
    int s = off[v], e = off[v + 1];
    float acc = 0.0f;
    for (int p = s; p < e; p++) {
        int ed = lst[p];
        acc += m[(size_t)(NNODE + ed) * HDIM + h];
    }
    agg[(size_t)v * HDIM + h] = acc;
}

// node_msgs: segment_sum(msgs, row) over n_nodes (CSR of row only)
__global__ void node_msgs_kernel(const float* __restrict__ msgs,
                                 const int* __restrict__ off, const int* __restrict__ lst,
                                 float* __restrict__ nm) {
    int v = blockIdx.x;
    int h = threadIdx.x;   // 64
    int s = off[v], e = off[v + 1];
    float acc = 0.0f;
    for (int p = s; p < e; p++) {
        int ed = lst[p];
        acc += msgs[(size_t)ed * MDIM + h];
    }
    nm[v * MDIM + h] = acc;
}

// fused GRU elementwise update (biases already added in GEMM epilogue)
__global__ void gru_kernel(const float* __restrict__ gi, const float* __restrict__ gh,
                           float* __restrict__ x) {
    int idx = blockIdx.x * blockDim.x + threadIdx.x;
    int n = idx >> 7, h = idx & 127;
    size_t b = (size_t)n * H3;
    float ir = gi[b + h],        hr = gh[b + h];
    float iz = gi[b + HDIM + h], hz = gh[b + HDIM + h];
    float in_ = gi[b + 2 * HDIM + h], hn = gh[b + 2 * HDIM + h];
    float r = 1.0f / (1.0f + expf(-(ir + hr)));
    float z = 1.0f / (1.0f + expf(-(iz + hz)));
    float nn = tanhf(in_ + r * hn);
    x[(size_t)idx] = (1.0f - z) * nn + z * x[(size_t)idx];
}

// ================= tensor-core GEMM: mma.sync bf16, bf16x3 fp32 emulation ====
// C[M, N] = A[M,128] * Bt[N,128]^T (+bias, optional relu)
// a = a_hi + a_lo (both bf16); acc += hi*hi + hi*lo + lo*hi  (fp32 accum).
// 256 threads = 8 warps (2m x 4n), block tile 128 x BN, warp tile 64 x (BN/4).
// K staged in 4 chunks of 32. SMEM rows padded to 40 bf16 (80B) -> ldmatrix
// row-start banks 20r mod 32 all distinct: conflict-free.

__device__ __forceinline__ uint32_t smem_u32(const void* p) {
    uint32_t a;
    asm("{ .reg .u64 t; cvta.to.shared.u64 t, %1; cvt.u32.u64 %0, t; }" : "=r"(a) : "l"(p));
    return a;
}
__device__ __forceinline__ void ldsm4(uint32_t* r, const void* p) {
    uint32_t addr = smem_u32(p);
    asm volatile("ldmatrix.sync.aligned.m8n8.x4.shared.b16 {%0,%1,%2,%3}, [%4];"
                 : "=r"(r[0]), "=r"(r[1]), "=r"(r[2]), "=r"(r[3]) : "r"(addr));
}
__device__ __forceinline__ void mma16816(float* c, const uint32_t* a, const uint32_t* b) {
    asm volatile(
        "mma.sync.aligned.m16n8k16.row.col.f32.bf16.bf16.f32 "
        "{%0,%1,%2,%3}, {%4,%5,%6,%7}, {%8,%9}, {%0,%1,%2,%3};"
        : "+f"(c[0]), "+f"(c[1]), "+f"(c[2]), "+f"(c[3])
        : "r"(a[0]), "r"(a[1]), "r"(a[2]), "r"(a[3]), "r"(b[0]), "r"(b[1]));
}

#define ROWP 40   // padded row length in bf16 elements (32 data + 8 pad)

template<int BN>
__global__ void __launch_bounds__(256, 2)
gemm_bf16x3_kernel(const float* __restrict__ A, const float* __restrict__ Bt,
                   const float* __restrict__ bias, float* __restrict__ C,
                   int ldc, int relu) {
    constexpr int WN = BN / 4;    // warp n extent: 32 or 16
    constexpr int NF = WN / 8;    // n8 fragments per warp: 4 or 2
    constexpr int NG = WN / 16;   // ldmatrix x4 groups per warp: 2 or 1

    __shared__ __nv_bfloat16 Ah[128 * ROWP], Al[128 * ROWP];
    __shared__ __nv_bfloat16 Bh[BN * ROWP],  Bl[BN * ROWP];

    int tid = threadIdx.x, lane = tid & 31, wid = tid >> 5;
    int wm = wid >> 2, wn = wid & 3;
    int bn = blockIdx.x * BN;
    int bm = blockIdx.y * 128;

    float acc[4][NF][4];
#pragma unroll
    for (int mt = 0; mt < 4; mt++)
#pragma unroll
        for (int nf = 0; nf < NF; nf++)
#pragma unroll
            for (int j = 0; j < 4; j++) acc[mt][nf][j] = 0.0f;

    // ldmatrix per-lane address components
    int t8 = lane >> 3, lr = lane & 7;
    int atm = lr + 8 * (t8 & 1), atk0 = (t8 >> 1) * 8;   // A: tiles (m-half, k-half)
    int btn = lr + 8 * (t8 >> 1), btk0 = (t8 & 1) * 8;   // B: tiles (k-half, n-half)

    for (int kc = 0; kc < 4; kc++) {
        // ---- load + split A chunk: 128 rows x 32 cols = 1024 quads ----
#pragma unroll
        for (int i = 0; i < 4; i++) {
            int idx = tid + i * 256;
            int r = idx >> 3, c4 = idx & 7;
            float4 v = *(const float4*)&A[(size_t)(bm + r) * HDIM + kc * 32 + c4 * 4];
            __nv_bfloat162 h0 = __floats2bfloat162_rn(v.x, v.y);
            __nv_bfloat162 h1 = __floats2bfloat162_rn(v.z, v.w);
            __nv_bfloat162 l0 = __floats2bfloat162_rn(v.x - __low2float(h0),
                                                      v.y - __high2float(h0));
            __nv_bfloat162 l1 = __floats2bfloat162_rn(v.z - __low2float(h1),
                                                      v.w - __high2float(h1));
            int o = r * (ROWP / 2) + c4 * 2;
            ((__nv_bfloat162*)Ah)[o] = h0; ((__nv_bfloat162*)Ah)[o + 1] = h1;
            ((__nv_bfloat162*)Al)[o] = l0; ((__nv_bfloat162*)Al)[o + 1] = l1;
        }
        // ---- load + split B chunk: BN rows x 32 cols = BN*8 quads ----
#pragma unroll
        for (int i = 0; i < BN / 32; i++) {   // FIX: was BN/64 (half of B never loaded)
            int idx = tid + i * 256;
            int r = idx >> 3, c4 = idx & 7;
            float4 v = *(const float4*)&Bt[(size_t)(bn + r) * HDIM + kc * 32 + c4 * 4];
            __nv_bfloat162 h0 = __floats2bfloat162_rn(v.x, v.y);
            __nv_bfloat162 h1 = __floats2bfloat162_rn(v.z, v.w);
            __nv_bfloat162 l0 = __floats2bfloat162_rn(v.x - __low2float(h0),
                                                      v.y - __high2float(h0));
            __nv_bfloat162 l1 = __floats2bfloat162_rn(v.z - __low2float(h1),
                                                      v.w - __high2float(h1));
            int o = r * (ROWP / 2) + c4 * 2;
            ((__nv_bfloat162*)Bh)[o] = h0; ((__nv_bfloat162*)Bh)[o + 1] = h1;
            ((__nv_bfloat162*)Bl)[o] = l0; ((__nv_bfloat162*)Bl)[o + 1] = l1;
        }
        __syncthreads();

#pragma unroll
        for (int ks = 0; ks < 2; ks++) {
            uint32_t afh[4][4], afl[4][4], bfh[NG][4], bfl[NG][4];
            int ak = ks * 16 + atk0;
            int bk = ks * 16 + btk0;
#pragma unroll
            for (int mt = 0; mt < 4; mt++) {
                int row = wm * 64 + mt * 16 + atm;
                ldsm4(afh[mt], &Ah[row * ROWP + ak]);
                ldsm4(afl[mt], &Al[row * ROWP + ak]);
            }
#pragma unroll
            for (int ng = 0; ng < NG; ng++) {
                int row = wn * WN + ng * 16 + btn;
                ldsm4(bfh[ng], &Bh[row * ROWP + bk]);
                ldsm4(bfl[ng], &Bl[row * ROWP + bk]);
            }
#pragma unroll
            for (int mt = 0; mt < 4; mt++)
#pragma unroll
                for (int nf = 0; nf < NF; nf++) {
                    const uint32_t* bh = &bfh[nf >> 1][2 * (nf & 1)];
                    const uint32_t* bl = &bfl[nf >> 1][2 * (nf & 1)];
                    mma16816(acc[mt][nf], afh[mt], bh);
                    mma16816(acc[mt][nf], afh[mt], bl);
                    mma16816(acc[mt][nf], afl[mt], bh);
                }
        }
        __syncthreads();
    }

    // ---- epilogue: c-frag rows lane/4 (+8), cols 2*(lane%4) (+1) ----
#pragma unroll
    for (int mt = 0; mt < 4; mt++) {
        int r0 = bm + wm * 64 + mt * 16 + (lane >> 2);
#pragma unroll
        for (int nf = 0; nf < NF; nf++) {
            int col = bn + wn * WN + nf * 8 + 2 * (lane & 3);
            float b0 = bias ? bias[col] : 0.0f;
            float b1 = bias ? bias[col + 1] : 0.0f;
            float v0 = acc[mt][nf][0] + b0, v1 = acc[mt][nf][1] + b1;
            float v2 = acc[mt][nf][2] + b0, v3 = acc[mt][nf][3] + b1;
            if (relu) {
                v0 = fmaxf(v0, 0.f); v1 = fmaxf(v1, 0.f);
                v2 = fmaxf(v2, 0.f); v3 = fmaxf(v3, 0.f);
            }
            *(float2*)&C[(size_t)r0 * ldc + col]       = make_float2(v0, v1);
            *(float2*)&C[(size_t)(r0 + 8) * ldc + col] = make_float2(v2, v3);
        }
    }
}

// ---------------- fused readout: 2 dense layers + logits + softmax ----------------
#define NPB 16
__global__ void readout_kernel(const float* __restrict__ nm,
                               const float* __restrict__ W1, const float* __restrict__ b1,
                               const float* __restrict__ W2, const float* __restrict__ b2,
                               const float* __restrict__ W3, const float* __restrict__ b3,
                               float* __restrict__ out) {
    __shared__ float nms[64], h1s[128], h2s[128], red[128];
    __shared__ float l0sh;
    int t = threadIdx.x;   // 128
    int v0 = blockIdx.x * NPB;
    for (int v = v0; v < v0 + NPB; v++) {
        if (t < 64) nms[t] = nm[v * MDIM + t];
        __syncthreads();
        float a = b1[t];
#pragma unroll 4
        for (int k = 0; k < 64; k++) a += nms[k] * W1[k * 128 + t];
        h1s[t] = fmaxf(a, 0.f);
        __syncthreads();
        float c = b2[t];
#pragma unroll 4
        for (int k = 0; k < 128; k++) c += h1s[k] * W2[k * 128 + t];
        h2s[t] = fmaxf(c, 0.f);
        __syncthreads();
        red[t] = h2s[t] * W3[2 * t + 0];
        __syncthreads();
        for (int s = 64; s > 0; s >>= 1) {
            if (t < s) red[t] += red[t + s];
            __syncthreads();
        }
        if (t == 0) l0sh = red[0] + b3[0];
        __syncthreads();
        red[t] = h2s[t] * W3[2 * t + 1];
        __syncthreads();
        for (int s = 64; s > 0; s >>= 1) {
            if (t < s) red[t] += red[t + s];
            __syncthreads();
        }
        if (t == 0) {
            float l0 = l0sh;
            float l1 = red[0] + b3[1];
            float mx = fmaxf(l0, l1);
            float e0 = expf(l0 - mx), e1 = expf(l1 - mx);
            float s_ = e0 + e1;
            out[v * 2 + 0] = e0 / s_;
            out[v * 2 + 1] = e1 / s_;
        }
        __syncthreads();
    }
}

// ---------------- launch ----------------
extern "C" void kernel_launch(void* const* d_in, const int* in_sizes, int n_in,
                              void* d_out, int out_size) {
    const float* jvals = (const float*)d_in[0];
    // d_in[1] = b (unused: only defines n_nodes)
    const int* row = (const int*)d_in[2];
    const int* col = (const int*)d_in[3];
    const float* convW  = (const float*)d_in[4];
    const float* gru_wi = (const float*)d_in[5];
    const float* gru_wh = (const float*)d_in[6];
    const float* gru_bi = (const float*)d_in[7];
    const float* gru_bh = (const float*)d_in[8];
    const float* mp_W1 = (const float*)d_in[9];
    const float* mp_b1 = (const float*)d_in[10];
    const float* mp_W2 = (const float*)d_in[11];
    const float* mp_b2 = (const float*)d_in[12];
    const float* mp_W3 = (const float*)d_in[13];
    const float* mp_b3 = (const float*)d_in[14];
    const float* ro_W1 = (const float*)d_in[15];
    const float* ro_b1 = (const float*)d_in[16];
    const float* ro_W2 = (const float*)d_in[17];
    const float* ro_b2 = (const float*)d_in[18];
    const float* ro_W3 = (const float*)d_in[19];
    const float* ro_b3 = (const float*)d_in[20];
    float* out = (float*)d_out;

    float *x, *m, *agg, *gi, *gh, *nm, *wt;
    int *degv, *offv, *curv, *lstv, *degr, *offr, *curr, *lstr;
    cudaGetSymbolAddress((void**)&x,   g_x);
    cudaGetSymbolAddress((void**)&m,   g_m);
    cudaGetSymbolAddress((void**)&agg, g_agg);
    cudaGetSymbolAddress((void**)&gi,  g_gi);
    cudaGetSymbolAddress((void**)&gh,  g_gh);
    cudaGetSymbolAddress((void**)&nm,  g_nm);
    cudaGetSymbolAddress((void**)&wt,  g_wt);
    cudaGetSymbolAddress((void**)&degv, g_deg_var);
    cudaGetSymbolAddress((void**)&offv, g_off_var);
    cudaGetSymbolAddress((void**)&curv, g_cur_var);
    cudaGetSymbolAddress((void**)&lstv, g_lst_var);
    cudaGetSymbolAddress((void**)&degr, g_deg_row);
    cudaGetSymbolAddress((void**)&offr, g_off_row);
    cudaGetSymbolAddress((void**)&curr, g_cur_row);
    cudaGetSymbolAddress((void**)&lstr, g_lst_row);

    float* wt_conv0 = wt;
    float* wt_conv1 = wt + 16384;
    float* wt_mp1   = wt + 32768;
    float* wt_mp2   = wt + 49152;
    float* wt_mp3   = wt + 65536;

    // ---- CSR build ----
    zero_deg_kernel<<<NNODE / 256, 256>>>(degv, degr);
    count_kernel<<<NEDGE / 256, 256>>>(row, col, degv, degr);
    scan_kernel<<<1, 1024>>>(degv, offv);
    scan_kernel<<<1, 1024>>>(degr, offr);
    copy_cur_kernel<<<NNODE / 256, 256>>>(offv, curv, offr, curr);
    scatter_kernel<<<NEDGE / 256, 256>>>(row, col, curv, lstv, curr, lstr);

    // ---- transpose NN weights to N-major ----
    transpose_kernel<<<(128 * 128) / 256, 256>>>(convW,         wt_conv0, 128, 128);
    transpose_kernel<<<(128 * 128) / 256, 256>>>(convW + 16384, wt_conv1, 128, 128);
    transpose_kernel<<<(128 * 128) / 256, 256>>>(mp_W1,         wt_mp1,   128, 128);
    transpose_kernel<<<(128 * 128) / 256, 256>>>(mp_W2,         wt_mp2,   128, 128);
    transpose_kernel<<<(128 * 64) / 256, 256>>>(mp_W3,          wt_mp3,   128, 64);

    // ---- init x ----
    init_x_kernel<<<(NTOT * HDIM) / 256, 256>>>(x, jvals);

    // ---- 2 GGNN layers ----
    for (int l = 0; l < 2; l++) {
        const float* wcv = l ? wt_conv1 : wt_conv0;
        // m = x @ conv_W[l]
        gemm_bf16x3_kernel<128><<<dim3(1, NTOT / 128), 256>>>(
            x, wcv, nullptr, m, 128, 0);
        // agg = segment_sum(m[src], dst)
        factor_agg_kernel<<<(NEDGE * 32) / 128, 128>>>(m, row, col, agg);
        var_agg_kernel<<<NNODE, 128>>>(m, offv, lstv, agg);
        // gi = agg @ wi^T + bi, gh = x @ wh^T + bh  (wi/wh already N-major)
        gemm_bf16x3_kernel<128><<<dim3(3, NTOT / 128), 256>>>(
            agg, gru_wi, gru_bi, gi, 384, 0);
        gemm_bf16x3_kernel<128><<<dim3(3, NTOT / 128), 256>>>(
            x, gru_wh, gru_bh, gh, 384, 0);
        gru_kernel<<<(NTOT * HDIM) / 256, 256>>>(gi, gh, x);
    }

    // ---- edge MLP on factor rows ----
    const float* xf = x + (size_t)NNODE * HDIM;
    gemm_bf16x3_kernel<128><<<dim3(1, NEDGE / 128), 256>>>(
        xf, wt_mp1, mp_b1, m, 128, 1);
    gemm_bf16x3_kernel<128><<<dim3(1, NEDGE / 128), 256>>>(
        m, wt_mp2, mp_b2, agg, 128, 1);
    gemm_bf16x3_kernel<64><<<dim3(1, NEDGE / 128), 256>>>(
        agg, wt_mp3, mp_b3, gi, 64, 0);

    // ---- node_msgs = segment_sum(msgs, row) ----
    node_msgs_kernel<<<NNODE, 64>>>(gi, offr, lstr, nm);

    // ---- readout + softmax ----
    readout_kernel<<<NNODE / NPB, 128>>>(nm, ro_W1, ro_b1, ro_W2, ro_b2, ro_W3, ro_b3, out);
}

// round 16
// speedup vs baseline: 2.1792x; 1.0191x over previous
#include <cuda_runtime.h>
#include <cuda_bf16.h>
#include <math.h>
#include <stdint.h>

// Problem constants
#define NNODE 8192
#define NEDGE 131072
#define NTOT  (NNODE + NEDGE)   // 139264
#define HDIM  128
#define H3    384
#define MDIM  64

// ---------------- device scratch (static globals: allowed) ----------------
__device__ float g_x  [(size_t)NTOT * HDIM];
__device__ float g_m  [(size_t)NTOT * HDIM];   // reused as hm1
__device__ float g_agg[(size_t)NTOT * HDIM];   // reused as hm2
__device__ float g_gi [(size_t)NTOT * H3];     // reused as msgs
__device__ float g_nm [NNODE * MDIM];
// transposed (N-major) weights: conv0, conv1, mp1, mp2, mp3
__device__ float g_wt [4 * 128 * 128 + 64 * 128];
// pre-split GRU weights (N-major 384x128), bf16 hi/lo
__device__ __nv_bfloat16 g_wih[H3 * HDIM], g_wil[H3 * HDIM];
__device__ __nv_bfloat16 g_whh[H3 * HDIM], g_whl[H3 * HDIM];

__device__ int g_deg_var[NNODE], g_off_var[NNODE + 1], g_cur_var[NNODE];
__device__ int g_lst_var[2 * NEDGE];
__device__ int g_deg_row[NNODE], g_off_row[NNODE + 1], g_cur_row[NNODE];
__device__ int g_lst_row[NEDGE];

// ---------------- small helper kernels ----------------
__global__ void zero_deg_kernel(int* degv, int* degr) {
    int i = blockIdx.x * blockDim.x + threadIdx.x;
    if (i < NNODE) { degv[i] = 0; degr[i] = 0; }
}

__global__ void count_kernel(const int* __restrict__ row, const int* __restrict__ col,
                             int* degv, int* degr) {
    int e = blockIdx.x * blockDim.x + threadIdx.x;
    if (e < NEDGE) {
        atomicAdd(&degv[row[e]], 1);
        atomicAdd(&degv[col[e]], 1);
        atomicAdd(&degr[row[e]], 1);
    }
}

// exclusive scan of 8192 ints with one 1024-thread block (8 per thread)
__global__ void scan_kernel(const int* __restrict__ deg, int* __restrict__ off) {
    __shared__ int sm[1024];
    int t = threadIdx.x;
    int v[8], pre[8];
    int s = 0;
#pragma unroll
    for (int i = 0; i < 8; i++) {
        v[i] = deg[t * 8 + i];
        pre[i] = s;
        s += v[i];
    }
    sm[t] = s;
    __syncthreads();
    for (int d = 1; d < 1024; d <<= 1) {
        int add = 0;
        if (t >= d) add = sm[t - d];
        __syncthreads();
        sm[t] += add;
        __syncthreads();
    }
    int base = (t == 0) ? 0 : sm[t - 1];
#pragma unroll
    for (int i = 0; i < 8; i++) off[t * 8 + i] = base + pre[i];
    if (t == 1023) off[8192] = sm[1023];
}

__global__ void copy_cur_kernel(const int* offv, int* curv, const int* offr, int* curr) {
    int i = blockIdx.x * blockDim.x + threadIdx.x;
    if (i < NNODE) { curv[i] = offv[i]; curr[i] = offr[i]; }
}

__global__ void scatter_kernel(const int* __restrict__ row, const int* __restrict__ col,
                               int* curv, int* lstv, int* curr, int* lstr) {
    int e = blockIdx.x * blockDim.x + threadIdx.x;
    if (e < NEDGE) {
        int r = row[e], c = col[e];
        int p = atomicAdd(&curv[r], 1); lstv[p] = e;
        int q = atomicAdd(&curv[c], 1); lstv[q] = e;
        int u = atomicAdd(&curr[r], 1); lstr[u] = e;
    }
}

__global__ void init_x_kernel(float* __restrict__ x, const float* __restrict__ jvals) {
    int idx = blockIdx.x * blockDim.x + threadIdx.x;
    int n = idx >> 7, h = idx & 127;
    float v = 0.0f;
    if (n >= NNODE) {
        if (h == 0) v = 1.0f;
        else if (h == 1) v = jvals[n - NNODE];
    }
    x[(size_t)idx] = v;
}

// transpose: in is K x N row-major -> out is N x K row-major
__global__ void transpose_kernel(const float* __restrict__ in, float* __restrict__ out,
                                 int K, int N) {
    int idx = blockIdx.x * blockDim.x + threadIdx.x;
    if (idx < K * N) {
        int k = idx / N, n = idx % N;
        out[n * K + k] = in[idx];
    }
}

// split fp32 weights into bf16 hi/lo
__global__ void split_w_kernel(const float* __restrict__ w,
                               __nv_bfloat16* __restrict__ hi,
                               __nv_bfloat16* __restrict__ lo, int n) {
    int idx = blockIdx.x * blockDim.x + threadIdx.x;
    if (idx < n) {
        float v = w[idx];
        __nv_bfloat16 h = __float2bfloat16(v);
        hi[idx] = h;
        lo[idx] = __float2bfloat16(v - __bfloat162float(h));
    }
}

// agg for factor rows: agg[NNODE+e] = m[row[e]] + m[col[e]]
__global__ void factor_agg_kernel(const float* __restrict__ m,
                                  const int* __restrict__ row, const int* __restrict__ col,
                                  float* __restrict__ agg) {
    int t = blockIdx.x * blockDim.x + threadIdx.x;
    int e = t >> 5, q = t & 31;
    const float4* m4 = (const float4*)m;
    float4* a4 = (float4*)agg;
    int r = row[e], c = col[e];
    float4 a = m4[(size_t)r * 32 + q];
    float4 b = m4[(size_t)c * 32 + q];
    a4[(size_t)(NNODE + e) * 32 + q] = make_float4(a.x + b.x, a.y + b.y, a.z + b.z, a.w + b.w);
}

// agg for variable rows: sum over incident factor messages (CSR)
__global__ void var_agg_kernel(const float* __restrict__ m,
                               const int* __restrict__ off, const int* __restrict__ lst,
                               float* __restrict__ agg) {
    int v = blockIdx.x;
    int h = threadIdx.x;
    int s = off[v], e = off[v + 1];
    float acc = 0.0f;
    for (int p = s; p < e; p++) {
        int ed = lst[p];
        acc += m[(size_t)(NNODE + ed) * HDIM + h];
    }
    agg[(size_t)v * HDIM + h] = acc;
}

// node_msgs: segment_sum(msgs, row) over n_nodes (CSR of row only)
__global__ void node_msgs_kernel(const float* __restrict__ msgs,
                                 const int* __restrict__ off, const int* __restrict__ lst,
                                 float* __restrict__ nm) {
    int v = blockIdx.x;
    int h = threadIdx.x;   // 64
    int s = off[v], e = off[v + 1];
    float acc = 0.0f;
    for (int p = s; p < e; p++) {
        int ed = lst[p];
        acc += msgs[(size_t)ed * MDIM + h];
    }
    nm[v * MDIM + h] = acc;
}

// ---------------- tensor-core primitives ----------------
__device__ __forceinline__ uint32_t smem_u32(const void* p) {
    uint32_t a;
    asm("{ .reg .u64 t; cvta.to.shared.u64 t, %1; cvt.u32.u64 %0, t; }" : "=r"(a) : "l"(p));
    return a;
}
__device__ __forceinline__ void ldsm4(uint32_t* r, const void* p) {
    uint32_t addr = smem_u32(p);
    asm volatile("ldmatrix.sync.aligned.m8n8.x4.shared.b16 {%0,%1,%2,%3}, [%4];"
                 : "=r"(r[0]), "=r"(r[1]), "=r"(r[2]), "=r"(r[3]) : "r"(addr));
}
__device__ __forceinline__ void mma16816(float* c, const uint32_t* a, const uint32_t* b) {
    asm volatile(
        "mma.sync.aligned.m16n8k16.row.col.f32.bf16.bf16.f32 "
        "{%0,%1,%2,%3}, {%4,%5,%6,%7}, {%8,%9}, {%0,%1,%2,%3};"
        : "+f"(c[0]), "+f"(c[1]), "+f"(c[2]), "+f"(c[3])
        : "r"(a[0]), "r"(a[1]), "r"(a[2]), "r"(a[3]), "r"(b[0]), "r"(b[1]));
}
__device__ __forceinline__ float sigm(float v) { return 1.0f / (1.0f + expf(-v)); }

#define ROWP 40   // padded row length in bf16 elements (32 data + 8 pad)

// ================= generic tensor GEMM (conv / mp layers) ====================
template<int BN>
__global__ void __launch_bounds__(256, 2)
gemm_bf16x3_kernel(const float* __restrict__ A, const float* __restrict__ Bt,
                   const float* __restrict__ bias, float* __restrict__ C,
                   int ldc, int relu) {
    constexpr int WN = BN / 4;
    constexpr int NF = WN / 8;
    constexpr int NG = WN / 16;

    __shared__ __nv_bfloat16 Ah[128 * ROWP], Al[128 * ROWP];
    __shared__ __nv_bfloat16 Bh[BN * ROWP],  Bl[BN * ROWP];

    int tid = threadIdx.x, lane = tid & 31, wid = tid >> 5;
    int wm = wid >> 2, wn = wid & 3;
    int bn = blockIdx.x * BN;
    int bm = blockIdx.y * 128;

    float acc[4][NF][4];
#pragma unroll
    for (int mt = 0; mt < 4; mt++)
#pragma unroll
        for (int nf = 0; nf < NF; nf++)
#pragma unroll
            for (int j = 0; j < 4; j++) acc[mt][nf][j] = 0.0f;

    int t8 = lane >> 3, lr = lane & 7;
    int atm = lr + 8 * (t8 & 1), atk0 = (t8 >> 1) * 8;
    int btn = lr + 8 * (t8 >> 1), btk0 = (t8 & 1) * 8;

    for (int kc = 0; kc < 4; kc++) {
#pragma unroll
        for (int i = 0; i < 4; i++) {
            int idx = tid + i * 256;
            int r = idx >> 3, c4 = idx & 7;
            float4 v = *(const float4*)&A[(size_t)(bm + r) * HDIM + kc * 32 + c4 * 4];
            __nv_bfloat162 h0 = __floats2bfloat162_rn(v.x, v.y);
            __nv_bfloat162 h1 = __floats2bfloat162_rn(v.z, v.w);
            __nv_bfloat162 l0 = __floats2bfloat162_rn(v.x - __low2float(h0),
                                                      v.y - __high2float(h0));
            __nv_bfloat162 l1 = __floats2bfloat162_rn(v.z - __low2float(h1),
                                                      v.w - __high2float(h1));
            int o = r * (ROWP / 2) + c4 * 2;
            ((__nv_bfloat162*)Ah)[o] = h0; ((__nv_bfloat162*)Ah)[o + 1] = h1;
            ((__nv_bfloat162*)Al)[o] = l0; ((__nv_bfloat162*)Al)[o + 1] = l1;
        }
#pragma unroll
        for (int i = 0; i < BN / 32; i++) {
            int idx = tid + i * 256;
            int r = idx >> 3, c4 = idx & 7;
            float4 v = *(const float4*)&Bt[(size_t)(bn + r) * HDIM + kc * 32 + c4 * 4];
            __nv_bfloat162 h0 = __floats2bfloat162_rn(v.x, v.y);
            __nv_bfloat162 h1 = __floats2bfloat162_rn(v.z, v.w);
            __nv_bfloat162 l0 = __floats2bfloat162_rn(v.x - __low2float(h0),
                                                      v.y - __high2float(h0));
            __nv_bfloat162 l1 = __floats2bfloat162_rn(v.z - __low2float(h1),
                                                      v.w - __high2float(h1));
            int o = r * (ROWP / 2) + c4 * 2;
            ((__nv_bfloat162*)Bh)[o] = h0; ((__nv_bfloat162*)Bh)[o + 1] = h1;
            ((__nv_bfloat162*)Bl)[o] = l0; ((__nv_bfloat162*)Bl)[o + 1] = l1;
        }
        __syncthreads();

#pragma unroll
        for (int ks = 0; ks < 2; ks++) {
            uint32_t afh[4][4], afl[4][4], bfh[NG][4], bfl[NG][4];
            int ak = ks * 16 + atk0;
            int bk = ks * 16 + btk0;
#pragma unroll
            for (int mt = 0; mt < 4; mt++) {
                int row = wm * 64 + mt * 16 + atm;
                ldsm4(afh[mt], &Ah[row * ROWP + ak]);
                ldsm4(afl[mt], &Al[row * ROWP + ak]);
            }
#pragma unroll
            for (int ng = 0; ng < NG; ng++) {
                int row = wn * WN + ng * 16 + btn;
                ldsm4(bfh[ng], &Bh[row * ROWP + bk]);
                ldsm4(bfl[ng], &Bl[row * ROWP + bk]);
            }
#pragma unroll
            for (int mt = 0; mt < 4; mt++)
#pragma unroll
                for (int nf = 0; nf < NF; nf++) {
                    const uint32_t* bh = &bfh[nf >> 1][2 * (nf & 1)];
                    const uint32_t* bl = &bfl[nf >> 1][2 * (nf & 1)];
                    mma16816(acc[mt][nf], afh[mt], bh);
                    mma16816(acc[mt][nf], afh[mt], bl);
                    mma16816(acc[mt][nf], afl[mt], bh);
                }
        }
        __syncthreads();
    }

#pragma unroll
    for (int mt = 0; mt < 4; mt++) {
        int r0 = bm + wm * 64 + mt * 16 + (lane >> 2);
#pragma unroll
        for (int nf = 0; nf < NF; nf++) {
            int col = bn + wn * WN + nf * 8 + 2 * (lane & 3);
            float b0 = bias ? bias[col] : 0.0f;
            float b1 = bias ? bias[col + 1] : 0.0f;
            float v0 = acc[mt][nf][0] + b0, v1 = acc[mt][nf][1] + b1;
            float v2 = acc[mt][nf][2] + b0, v3 = acc[mt][nf][3] + b1;
            if (relu) {
                v0 = fmaxf(v0, 0.f); v1 = fmaxf(v1, 0.f);
                v2 = fmaxf(v2, 0.f); v3 = fmaxf(v3, 0.f);
            }
            *(float2*)&C[(size_t)r0 * ldc + col]       = make_float2(v0, v1);
            *(float2*)&C[(size_t)(r0 + 8) * ldc + col] = make_float2(v2, v3);
        }
    }
}

// ================= fused GRU: gi-GEMM + gh-GEMM + elementwise ================
// Per CTA: 64 rows. Accumulates s_r = agg@wi_r^T + x@wh_r^T (single acc; same
// for s_z), and i_n / h_n separately; applies GRU; updates x in place.
// gi/gh never touch HBM. 256 threads = 8 warps (2m x 4n), warp tile 32x32.
// Dynamic SMEM 60KB: A chunks (agg,x)x(hi,lo) 64x32 + B chunks (wi,wh)x(hi,lo)
// 128x32, all ROWP-padded bf16.

#define FSM_AAGG_H 0
#define FSM_AAGG_L (64 * ROWP)
#define FSM_AX_H   (2 * 64 * ROWP)
#define FSM_AX_L   (3 * 64 * ROWP)
#define FSM_BI_H   (4 * 64 * ROWP)
#define FSM_BI_L   (4 * 64 * ROWP + 128 * ROWP)
#define FSM_BH_H   (4 * 64 * ROWP + 2 * 128 * ROWP)
#define FSM_BH_L   (4 * 64 * ROWP + 3 * 128 * ROWP)
#define FSM_TOTAL  ((4 * 64 * ROWP + 4 * 128 * ROWP) * 2)   // bytes = 61440

__global__ void __launch_bounds__(256, 1)
gru_fused_kernel(const float* __restrict__ agg,
                 const __nv_bfloat16* __restrict__ wih, const __nv_bfloat16* __restrict__ wil,
                 const __nv_bfloat16* __restrict__ whh, const __nv_bfloat16* __restrict__ whl,
                 const float* __restrict__ bi, const float* __restrict__ bh,
                 float* __restrict__ x) {
    extern __shared__ __align__(16) char fsm[];
    __nv_bfloat16* AaggH = (__nv_bfloat16*)fsm + FSM_AAGG_H;
    __nv_bfloat16* AaggL = (__nv_bfloat16*)fsm + FSM_AAGG_L;
    __nv_bfloat16* AxH   = (__nv_bfloat16*)fsm + FSM_AX_H;
    __nv_bfloat16* AxL   = (__nv_bfloat16*)fsm + FSM_AX_L;
    __nv_bfloat16* BiH   = (__nv_bfloat16*)fsm + FSM_BI_H;
    __nv_bfloat16* BiL   = (__nv_bfloat16*)fsm + FSM_BI_L;
    __nv_bfloat16* BhH   = (__nv_bfloat16*)fsm + FSM_BH_H;
    __nv_bfloat16* BhL   = (__nv_bfloat16*)fsm + FSM_BH_L;

    int tid = threadIdx.x, lane = tid & 31, wid = tid >> 5;
    int wm = wid >> 2, wn = wid & 3;     // 2m x 4n
    int bm = blockIdx.x * 64;

    float a_r[2][4][4], a_z[2][4][4], a_i[2][4][4], a_h[2][4][4];
#pragma unroll
    for (int mt = 0; mt < 2; mt++)
#pragma unroll
        for (int nf = 0; nf < 4; nf++)
#pragma unroll
            for (int j = 0; j < 4; j++) {
                a_r[mt][nf][j] = 0.f; a_z[mt][nf][j] = 0.f;
                a_i[mt][nf][j] = 0.f; a_h[mt][nf][j] = 0.f;
            }

    int t8 = lane >> 3, lr = lane & 7;
    int atm = lr + 8 * (t8 & 1), atk0 = (t8 >> 1) * 8;
    int btn = lr + 8 * (t8 >> 1), btk0 = (t8 & 1) * 8;

    for (int kc = 0; kc < 4; kc++) {
        // ---- stage A chunks: agg and x, 64 rows x 32 cols each ----
#pragma unroll
        for (int i = 0; i < 2; i++) {
            int idx = tid + i * 256;
            int r = idx >> 3, c4 = idx & 7;
            int o = r * (ROWP / 2) + c4 * 2;
            {
                float4 v = *(const float4*)&agg[(size_t)(bm + r) * HDIM + kc * 32 + c4 * 4];
                __nv_bfloat162 h0 = __floats2bfloat162_rn(v.x, v.y);
                __nv_bfloat162 h1 = __floats2bfloat162_rn(v.z, v.w);
                __nv_bfloat162 l0 = __floats2bfloat162_rn(v.x - __low2float(h0),
                                                          v.y - __high2float(h0));
                __nv_bfloat162 l1 = __floats2bfloat162_rn(v.z - __low2float(h1),
                                                          v.w - __high2float(h1));
                ((__nv_bfloat162*)AaggH)[o] = h0; ((__nv_bfloat162*)AaggH)[o + 1] = h1;
                ((__nv_bfloat162*)AaggL)[o] = l0; ((__nv_bfloat162*)AaggL)[o + 1] = l1;
            }
            {
                float4 v = *(const float4*)&x[(size_t)(bm + r) * HDIM + kc * 32 + c4 * 4];
                __nv_bfloat162 h0 = __floats2bfloat162_rn(v.x, v.y);
                __nv_bfloat162 h1 = __floats2bfloat162_rn(v.z, v.w);
                __nv_bfloat162 l0 = __floats2bfloat162_rn(v.x - __low2float(h0),
                                                          v.y - __high2float(h0));
                __nv_bfloat162 l1 = __floats2bfloat162_rn(v.z - __low2float(h1),
                                                          v.w - __high2float(h1));
                ((__nv_bfloat162*)AxH)[o] = h0; ((__nv_bfloat162*)AxH)[o + 1] = h1;
                ((__nv_bfloat162*)AxL)[o] = l0; ((__nv_bfloat162*)AxL)[o + 1] = l1;
            }
        }
        __syncthreads();

#pragma unroll
        for (int g = 0; g < 3; g++) {
            // ---- stage B chunks for gate g: wi_g, wh_g (pre-split bf16) ----
#pragma unroll
            for (int i = 0; i < 2; i++) {
                int idx = tid + i * 256;
                int r = idx >> 2, c8 = idx & 3;   // r 0..127, 8 bf16 per ld
                size_t src = (size_t)(g * 128 + r) * HDIM + kc * 32 + c8 * 8;
                int dst = r * ROWP + c8 * 8;
                *(uint4*)&BiH[dst] = *(const uint4*)&wih[src];
                *(uint4*)&BiL[dst] = *(const uint4*)&wil[src];
                *(uint4*)&BhH[dst] = *(const uint4*)&whh[src];
                *(uint4*)&BhL[dst] = *(const uint4*)&whl[src];
            }
            __syncthreads();

#pragma unroll
            for (int ks = 0; ks < 2; ks++) {
                uint32_t agh[2][4], agl[2][4], axh[2][4], axl[2][4];
                uint32_t bih[2][4], bil[2][4], bhh2[2][4], bhl2[2][4];
                int ak = ks * 16 + atk0;
                int bk = ks * 16 + btk0;
#pragma unroll
                for (int mt = 0; mt < 2; mt++) {
                    int row = wm * 32 + mt * 16 + atm;
                    ldsm4(agh[mt], &AaggH[row * ROWP + ak]);
                    ldsm4(agl[mt], &AaggL[row * ROWP + ak]);
                    ldsm4(axh[mt], &AxH[row * ROWP + ak]);
                    ldsm4(axl[mt], &AxL[row * ROWP + ak]);
                }
#pragma unroll
                for (int ng = 0; ng < 2; ng++) {
                    int row = wn * 32 + ng * 16 + btn;
                    ldsm4(bih[ng],  &BiH[row * ROWP + bk]);
                    ldsm4(bil[ng],  &BiL[row * ROWP + bk]);
                    ldsm4(bhh2[ng], &BhH[row * ROWP + bk]);
                    ldsm4(bhl2[ng], &BhL[row * ROWP + bk]);
                }
#pragma unroll
                for (int mt = 0; mt < 2; mt++)
#pragma unroll
                    for (int nf = 0; nf < 4; nf++) {
                        const uint32_t* pih = &bih[nf >> 1][2 * (nf & 1)];
                        const uint32_t* pil = &bil[nf >> 1][2 * (nf & 1)];
                        const uint32_t* phh = &bhh2[nf >> 1][2 * (nf & 1)];
                        const uint32_t* phl = &bhl2[nf >> 1][2 * (nf & 1)];
                        if (g < 2) {
                            float* d = (g == 0) ? a_r[mt][nf] : a_z[mt][nf];
                            mma16816(d, agh[mt], pih);
                            mma16816(d, agh[mt], pil);
                            mma16816(d, agl[mt], pih);
                            mma16816(d, axh[mt], phh);
                            mma16816(d, axh[mt], phl);
                            mma16816(d, axl[mt], phh);
                        } else {
                            mma16816(a_i[mt][nf], agh[mt], pih);
                            mma16816(a_i[mt][nf], agh[mt], pil);
                            mma16816(a_i[mt][nf], agl[mt], pih);
                            mma16816(a_h[mt][nf], axh[mt], phh);
                            mma16816(a_h[mt][nf], axh[mt], phl);
                            mma16816(a_h[mt][nf], axl[mt], phh);
                        }
                    }
            }
            __syncthreads();
        }
    }

    // ---- epilogue: GRU elementwise, x updated in place ----
#pragma unroll
    for (int mt = 0; mt < 2; mt++) {
        int r0 = bm + wm * 32 + mt * 16 + (lane >> 2);
#pragma unroll
        for (int nf = 0; nf < 4; nf++) {
            int h = wn * 32 + nf * 8 + 2 * (lane & 3);
            float brz0 = bi[h] + bh[h],             brz1 = bi[h + 1] + bh[h + 1];
            float bzz0 = bi[128 + h] + bh[128 + h], bzz1 = bi[129 + h] + bh[129 + h];
            float bin0 = bi[256 + h], bin1 = bi[257 + h];
            float bhn0 = bh[256 + h], bhn1 = bh[257 + h];

            float2 x0 = *(const float2*)&x[(size_t)r0 * HDIM + h];
            float2 x1 = *(const float2*)&x[(size_t)(r0 + 8) * HDIM + h];

            float r00 = sigm(a_r[mt][nf][0] + brz0), r01 = sigm(a_r[mt][nf][1] + brz1);
            float r10 = sigm(a_r[mt][nf][2] + brz0), r11 = sigm(a_r[mt][nf][3] + brz1);
            float z00 = sigm(a_z[mt][nf][0] + bzz0), z01 = sigm(a_z[mt][nf][1] + bzz1);
            float z10 = sigm(a_z[mt][nf][2] + bzz0), z11 = sigm(a_z[mt][nf][3] + bzz1);
            float n00 = tanhf(a_i[mt][nf][0] + bin0 + r00 * (a_h[mt][nf][0] + bhn0));
            float n01 = tanhf(a_i[mt][nf][1] + bin1 + r01 * (a_h[mt][nf][1] + bhn1));
            float n10 = tanhf(a_i[mt][nf][2] + bin0 + r10 * (a_h[mt][nf][2] + bhn0));
            float n11 = tanhf(a_i[mt][nf][3] + bin1 + r11 * (a_h[mt][nf][3] + bhn1));

            float2 o0, o1;
            o0.x = (1.f - z00) * n00 + z00 * x0.x;
            o0.y = (1.f - z01) * n01 + z01 * x0.y;
            o1.x = (1.f - z10) * n10 + z10 * x1.x;
            o1.y = (1.f - z11) * n11 + z11 * x1.y;
            *(float2*)&x[(size_t)r0 * HDIM + h]       = o0;
            *(float2*)&x[(size_t)(r0 + 8) * HDIM + h] = o1;
        }
    }
}

// ---------------- fused readout: 2 dense layers + logits + softmax ----------------
#define NPB 16
__global__ void readout_kernel(const float* __restrict__ nm,
                               const float* __restrict__ W1, const float* __restrict__ b1,
                               const float* __restrict__ W2, const float* __restrict__ b2,
                               const float* __restrict__ W3, const float* __restrict__ b3,
                               float* __restrict__ out) {
    __shared__ float nms[64], h1s[128], h2s[128], red[128];
    __shared__ float l0sh;
    int t = threadIdx.x;   // 128
    int v0 = blockIdx.x * NPB;
    for (int v = v0; v < v0 + NPB; v++) {
        if (t < 64) nms[t] = nm[v * MDIM + t];
        __syncthreads();
        float a = b1[t];
#pragma unroll 4
        for (int k = 0; k < 64; k++) a += nms[k] * W1[k * 128 + t];
        h1s[t] = fmaxf(a, 0.f);
        __syncthreads();
        float c = b2[t];
#pragma unroll 4
        for (int k = 0; k < 128; k++) c += h1s[k] * W2[k * 128 + t];
        h2s[t] = fmaxf(c, 0.f);
        __syncthreads();
        red[t] = h2s[t] * W3[2 * t + 0];
        __syncthreads();
        for (int s = 64; s > 0; s >>= 1) {
            if (t < s) red[t] += red[t + s];
            __syncthreads();
        }
        if (t == 0) l0sh = red[0] + b3[0];
        __syncthreads();
        red[t] = h2s[t] * W3[2 * t + 1];
        __syncthreads();
        for (int s = 64; s > 0; s >>= 1) {
            if (t < s) red[t] += red[t + s];
            __syncthreads();
        }
        if (t == 0) {
            float l0 = l0sh;
            float l1 = red[0] + b3[1];
            float mx = fmaxf(l0, l1);
            float e0 = expf(l0 - mx), e1 = expf(l1 - mx);
            float s_ = e0 + e1;
            out[v * 2 + 0] = e0 / s_;
            out[v * 2 + 1] = e1 / s_;
        }
        __syncthreads();
    }
}

// ---------------- launch ----------------
extern "C" void kernel_launch(void* const* d_in, const int* in_sizes, int n_in,
                              void* d_out, int out_size) {
    const float* jvals = (const float*)d_in[0];
    // d_in[1] = b (unused: only defines n_nodes)
    const int* row = (const int*)d_in[2];
    const int* col = (const int*)d_in[3];
    const float* convW  = (const float*)d_in[4];
    const float* gru_wi = (const float*)d_in[5];
    const float* gru_wh = (const float*)d_in[6];
    const float* gru_bi = (const float*)d_in[7];
    const float* gru_bh = (const float*)d_in[8];
    const float* mp_W1 = (const float*)d_in[9];
    const float* mp_b1 = (const float*)d_in[10];
    const float* mp_W2 = (const float*)d_in[11];
    const float* mp_b2 = (const float*)d_in[12];
    const float* mp_W3 = (const float*)d_in[13];
    const float* mp_b3 = (const float*)d_in[14];
    const float* ro_W1 = (const float*)d_in[15];
    const float* ro_b1 = (const float*)d_in[16];
    const float* ro_W2 = (const float*)d_in[17];
    const float* ro_b2 = (const float*)d_in[18];
    const float* ro_W3 = (const float*)d_in[19];
    const float* ro_b3 = (const float*)d_in[20];
    float* out = (float*)d_out;

    float *x, *m, *agg, *gi, *nm, *wt;
    __nv_bfloat16 *wih, *wil, *whh, *whl;
    int *degv, *offv, *curv, *lstv, *degr, *offr, *curr, *lstr;
    cudaGetSymbolAddress((void**)&x,   g_x);
    cudaGetSymbolAddress((void**)&m,   g_m);
    cudaGetSymbolAddress((void**)&agg, g_agg);
    cudaGetSymbolAddress((void**)&gi,  g_gi);
    cudaGetSymbolAddress((void**)&nm,  g_nm);
    cudaGetSymbolAddress((void**)&wt,  g_wt);
    cudaGetSymbolAddress((void**)&wih, g_wih);
    cudaGetSymbolAddress((void**)&wil, g_wil);
    cudaGetSymbolAddress((void**)&whh, g_whh);
    cudaGetSymbolAddress((void**)&whl, g_whl);
    cudaGetSymbolAddress((void**)&degv, g_deg_var);
    cudaGetSymbolAddress((void**)&offv, g_off_var);
    cudaGetSymbolAddress((void**)&curv, g_cur_var);
    cudaGetSymbolAddress((void**)&lstv, g_lst_var);
    cudaGetSymbolAddress((void**)&degr, g_deg_row);
    cudaGetSymbolAddress((void**)&offr, g_off_row);
    cudaGetSymbolAddress((void**)&curr, g_cur_row);
    cudaGetSymbolAddress((void**)&lstr, g_lst_row);

    float* wt_conv0 = wt;
    float* wt_conv1 = wt + 16384;
    float* wt_mp1   = wt + 32768;
    float* wt_mp2   = wt + 49152;
    float* wt_mp3   = wt + 65536;

    cudaFuncSetAttribute(gru_fused_kernel,
                         cudaFuncAttributeMaxDynamicSharedMemorySize, FSM_TOTAL);

    // ---- CSR build ----
    zero_deg_kernel<<<NNODE / 256, 256>>>(degv, degr);
    count_kernel<<<NEDGE / 256, 256>>>(row, col, degv, degr);
    scan_kernel<<<1, 1024>>>(degv, offv);
    scan_kernel<<<1, 1024>>>(degr, offr);
    copy_cur_kernel<<<NNODE / 256, 256>>>(offv, curv, offr, curr);
    scatter_kernel<<<NEDGE / 256, 256>>>(row, col, curv, lstv, curr, lstr);

    // ---- weight prep: transpose NN weights; split GRU weights ----
    transpose_kernel<<<(128 * 128) / 256, 256>>>(convW,         wt_conv0, 128, 128);
    transpose_kernel<<<(128 * 128) / 256, 256>>>(convW + 16384, wt_conv1, 128, 128);
    transpose_kernel<<<(128 * 128) / 256, 256>>>(mp_W1,         wt_mp1,   128, 128);
    transpose_kernel<<<(128 * 128) / 256, 256>>>(mp_W2,         wt_mp2,   128, 128);
    transpose_kernel<<<(128 * 64) / 256, 256>>>(mp_W3,          wt_mp3,   128, 64);
    split_w_kernel<<<(H3 * HDIM) / 256, 256>>>(gru_wi, wih, wil, H3 * HDIM);
    split_w_kernel<<<(H3 * HDIM) / 256, 256>>>(gru_wh, whh, whl, H3 * HDIM);

    // ---- init x ----
    init_x_kernel<<<(NTOT * HDIM) / 256, 256>>>(x, jvals);

    // ---- 2 GGNN layers ----
    for (int l = 0; l < 2; l++) {
        const float* wcv = l ? wt_conv1 : wt_conv0;
        // m = x @ conv_W[l]
        gemm_bf16x3_kernel<128><<<dim3(1, NTOT / 128), 256>>>(
            x, wcv, nullptr, m, 128, 0);
        // agg = segment_sum(m[src], dst)
        factor_agg_kernel<<<(NEDGE * 32) / 128, 128>>>(m, row, col, agg);
        var_agg_kernel<<<NNODE, 128>>>(m, offv, lstv, agg);
        // fused GRU: gi/gh GEMMs + elementwise, x updated in place
        gru_fused_kernel<<<NTOT / 64, 256, FSM_TOTAL>>>(
            agg, wih, wil, whh, whl, gru_bi, gru_bh, x);
    }

    // ---- edge MLP on factor rows ----
    const float* xf = x + (size_t)NNODE * HDIM;
    gemm_bf16x3_kernel<128><<<dim3(1, NEDGE / 128), 256>>>(
        xf, wt_mp1, mp_b1, m, 128, 1);
    gemm_bf16x3_kernel<128><<<dim3(1, NEDGE / 128), 256>>>(
        m, wt_mp2, mp_b2, agg, 128, 1);
    gemm_bf16x3_kernel<64><<<dim3(1, NEDGE / 128), 256>>>(
        agg, wt_mp3, mp_b3, gi, 64, 0);

    // ---- node_msgs = segment_sum(msgs, row) ----
    node_msgs_kernel<<<NNODE, 64>>>(gi, offr, lstr, nm);

    // ---- readout + softmax ----
    readout_kernel<<<NNODE / NPB, 128>>>(nm, ro_W1, ro_b1, ro_W2, ro_b2, ro_W3, ro_b3, out);
}

// round 17
// speedup vs baseline: 3.3454x; 1.5351x over previous
#include <cuda_runtime.h>
#include <cuda_bf16.h>
#include <math.h>
#include <stdint.h>

// Problem constants
#define NNODE 8192
#define NEDGE 131072
#define NTOT  (NNODE + NEDGE)   // 139264
#define HDIM  128
#define H3    384
#define MDIM  64

// ---------------- device scratch (static globals: allowed) ----------------
__device__ float g_x  [(size_t)NTOT * HDIM];
__device__ float g_m  [(size_t)NTOT * HDIM];   // reused as hm1
__device__ float g_agg[(size_t)NTOT * HDIM];   // reused as hm2
__device__ float g_gi [(size_t)NTOT * H3];     // reused as msgs
__device__ float g_nm [NNODE * MDIM];
// transposed (N-major) weights: conv1, mp1, mp2, mp3
__device__ float g_wt [3 * 128 * 128 + 64 * 128];
// pre-split GRU weights (N-major 384x128), bf16 hi/lo
__device__ __nv_bfloat16 g_wih[H3 * HDIM], g_wil[H3 * HDIM];
__device__ __nv_bfloat16 g_whh[H3 * HDIM], g_whl[H3 * HDIM];
// layer-0 rank-2 precompute
__device__ float g_u0[H3], g_u1[H3], g_v0[H3], g_v1[H3];

__device__ int g_deg_var[NNODE], g_off_var[NNODE + 1], g_cur_var[NNODE];
__device__ int g_lst_var[2 * NEDGE];
__device__ int g_deg_row[NNODE], g_off_row[NNODE + 1], g_cur_row[NNODE];
__device__ int g_lst_row[NEDGE];

// ---------------- small helper kernels ----------------
__global__ void zero_deg_kernel(int* degv, int* degr) {
    int i = blockIdx.x * blockDim.x + threadIdx.x;
    if (i < NNODE) { degv[i] = 0; degr[i] = 0; }
}

__global__ void count_kernel(const int* __restrict__ row, const int* __restrict__ col,
                             int* degv, int* degr) {
    int e = blockIdx.x * blockDim.x + threadIdx.x;
    if (e < NEDGE) {
        atomicAdd(&degv[row[e]], 1);
        atomicAdd(&degv[col[e]], 1);
        atomicAdd(&degr[row[e]], 1);
    }
}

// exclusive scan of 8192 ints with one 1024-thread block (8 per thread)
__global__ void scan_kernel(const int* __restrict__ deg, int* __restrict__ off) {
    __shared__ int sm[1024];
    int t = threadIdx.x;
    int v[8], pre[8];
    int s = 0;
#pragma unroll
    for (int i = 0; i < 8; i++) {
        v[i] = deg[t * 8 + i];
        pre[i] = s;
        s += v[i];
    }
    sm[t] = s;
    __syncthreads();
    for (int d = 1; d < 1024; d <<= 1) {
        int add = 0;
        if (t >= d) add = sm[t - d];
        __syncthreads();
        sm[t] += add;
        __syncthreads();
    }
    int base = (t == 0) ? 0 : sm[t - 1];
#pragma unroll
    for (int i = 0; i < 8; i++) off[t * 8 + i] = base + pre[i];
    if (t == 1023) off[8192] = sm[1023];
}

__global__ void copy_cur_kernel(const int* offv, int* curv, const int* offr, int* curr) {
    int i = blockIdx.x * blockDim.x + threadIdx.x;
    if (i < NNODE) { curv[i] = offv[i]; curr[i] = offr[i]; }
}

__global__ void scatter_kernel(const int* __restrict__ row, const int* __restrict__ col,
                               int* curv, int* lstv, int* curr, int* lstr) {
    int e = blockIdx.x * blockDim.x + threadIdx.x;
    if (e < NEDGE) {
        int r = row[e], c = col[e];
        int p = atomicAdd(&curv[r], 1); lstv[p] = e;
        int q = atomicAdd(&curv[c], 1); lstv[q] = e;
        int u = atomicAdd(&curr[r], 1); lstr[u] = e;
    }
}

// transpose: in is K x N row-major -> out is N x K row-major
__global__ void transpose_kernel(const float* __restrict__ in, float* __restrict__ out,
                                 int K, int N) {
    int idx = blockIdx.x * blockDim.x + threadIdx.x;
    if (idx < K * N) {
        int k = idx / N, n = idx % N;
        out[n * K + k] = in[idx];
    }
}

// split fp32 weights into bf16 hi/lo
__global__ void split_w_kernel(const float* __restrict__ w,
                               __nv_bfloat16* __restrict__ hi,
                               __nv_bfloat16* __restrict__ lo, int n) {
    int idx = blockIdx.x * blockDim.x + threadIdx.x;
    if (idx < n) {
        float v = w[idx];
        __nv_bfloat16 h = __float2bfloat16(v);
        hi[idx] = h;
        lo[idx] = __float2bfloat16(v - __bfloat162float(h));
    }
}

// layer-0 precompute: u0 = convW0row0 @ wi^T, u1 = convW0row1 @ wi^T,
// v0 = wh[:,0], v1 = wh[:,1]
__global__ void prep_l0_kernel(const float* __restrict__ convW,
                               const float* __restrict__ wi,
                               const float* __restrict__ wh,
                               float* u0, float* u1, float* v0, float* v1) {
    int g = blockIdx.x * blockDim.x + threadIdx.x;
    if (g < H3) {
        float a0 = 0.f, a1 = 0.f;
        for (int j = 0; j < HDIM; j++) {
            float w = wi[g * HDIM + j];
            a0 += convW[j] * w;           // convW0[0][j]
            a1 += convW[HDIM + j] * w;    // convW0[1][j]
        }
        u0[g] = a0; u1[g] = a1;
        v0[g] = wh[g * HDIM];
        v1[g] = wh[g * HDIM + 1];
    }
}

__device__ __forceinline__ float sigm(float v) { return 1.0f / (1.0f + expf(-v)); }

// layer 0 fully elementwise (x rank-2 sparse at input):
//  var n:  gi = deg*u0 + S*u1 + bi ; gh = bh ; x_old = 0
//  fac e:  gi = bi ; gh = v0 + jv*v1 + bh ; x_old = [1, jv, 0, ...]
#define L0_NPB 16
__global__ void layer0_kernel(const float* __restrict__ jvals,
                              const int* __restrict__ offv, const int* __restrict__ lstv,
                              const float* __restrict__ u0, const float* __restrict__ u1,
                              const float* __restrict__ v0, const float* __restrict__ v1,
                              const float* __restrict__ bi, const float* __restrict__ bh,
                              float* __restrict__ x) {
    __shared__ float su0[H3], su1[H3], sv0[H3], sv1[H3], sbi[H3], sbh[H3];
    __shared__ float sS;
    int t = threadIdx.x;   // 128
    for (int g = t; g < H3; g += 128) {
        su0[g] = u0[g]; su1[g] = u1[g];
        sv0[g] = v0[g]; sv1[g] = v1[g];
        sbi[g] = bi[g]; sbh[g] = bh[g];
    }
    __syncthreads();
    int n0 = blockIdx.x * L0_NPB;
    for (int i = 0; i < L0_NPB; i++) {
        int n = n0 + i;
        float gr, gz, gn, hr, hz, hn, xold;
        if (n < NNODE) {
            if (t < 32) {
                int s = offv[n], e = offv[n + 1];
                float p = 0.f;
                for (int q = s + t; q < e; q += 32) p += jvals[lstv[q]];
#pragma unroll
                for (int o = 16; o; o >>= 1) p += __shfl_down_sync(0xffffffffu, p, o);
                if (t == 0) sS = p;
            }
            __syncthreads();
            float S = sS;
            float deg = (float)(offv[n + 1] - offv[n]);
            gr = deg * su0[t]       + S * su1[t]       + sbi[t];
            gz = deg * su0[128 + t] + S * su1[128 + t] + sbi[128 + t];
            gn = deg * su0[256 + t] + S * su1[256 + t] + sbi[256 + t];
            hr = sbh[t]; hz = sbh[128 + t]; hn = sbh[256 + t];
            xold = 0.f;
        } else {
            float jv = jvals[n - NNODE];
            gr = sbi[t]; gz = sbi[128 + t]; gn = sbi[256 + t];
            hr = sv0[t]       + jv * sv1[t]       + sbh[t];
            hz = sv0[128 + t] + jv * sv1[128 + t] + sbh[128 + t];
            hn = sv0[256 + t] + jv * sv1[256 + t] + sbh[256 + t];
            xold = (t == 0) ? 1.f : ((t == 1) ? jv : 0.f);
        }
        float r = sigm(gr + hr), z = sigm(gz + hz);
        float nn = tanhf(gn + r * hn);
        x[(size_t)n * HDIM + t] = (1.f - z) * nn + z * xold;
        __syncthreads();
    }
}

// agg for factor rows: agg[NNODE+e] = m[row[e]] + m[col[e]]
__global__ void factor_agg_kernel(const float* __restrict__ m,
                                  const int* __restrict__ row, const int* __restrict__ col,
                                  float* __restrict__ agg) {
    int t = blockIdx.x * blockDim.x + threadIdx.x;
    int e = t >> 5, q = t & 31;
    const float4* m4 = (const float4*)m;
    float4* a4 = (float4*)agg;
    int r = row[e], c = col[e];
    float4 a = m4[(size_t)r * 32 + q];
    float4 b = m4[(size_t)c * 32 + q];
    a4[(size_t)(NNODE + e) * 32 + q] = make_float4(a.x + b.x, a.y + b.y, a.z + b.z, a.w + b.w);
}

// agg for variable rows: sum over incident factor messages (CSR)
__global__ void var_agg_kernel(const float* __restrict__ m,
                               const int* __restrict__ off, const int* __restrict__ lst,
                               float* __restrict__ agg) {
    int v = blockIdx.x;
    int h = threadIdx.x;
    int s = off[v], e = off[v + 1];
    float acc = 0.0f;
    for (int p = s; p < e; p++) {
        int ed = lst[p];
        acc += m[(size_t)(NNODE + ed) * HDIM + h];
    }
    agg[(size_t)v * HDIM + h] = acc;
}

// node_msgs: segment_sum(msgs, row) over n_nodes (CSR of row only)
__global__ void node_msgs_kernel(const float* __restrict__ msgs,
                                 const int* __restrict__ off, const int* __restrict__ lst,
                                 float* __restrict__ nm) {
    int v = blockIdx.x;
    int h = threadIdx.x;   // 64
    int s = off[v], e = off[v + 1];
    float acc = 0.0f;
    for (int p = s; p < e; p++) {
        int ed = lst[p];
        acc += msgs[(size_t)ed * MDIM + h];
    }
    nm[v * MDIM + h] = acc;
}

// ---------------- tensor-core primitives ----------------
__device__ __forceinline__ uint32_t smem_u32(const void* p) {
    uint32_t a;
    asm("{ .reg .u64 t; cvta.to.shared.u64 t, %1; cvt.u32.u64 %0, t; }" : "=r"(a) : "l"(p));
    return a;
}
__device__ __forceinline__ void ldsm4(uint32_t* r, const void* p) {
    uint32_t addr = smem_u32(p);
    asm volatile("ldmatrix.sync.aligned.m8n8.x4.shared.b16 {%0,%1,%2,%3}, [%4];"
                 : "=r"(r[0]), "=r"(r[1]), "=r"(r[2]), "=r"(r[3]) : "r"(addr));
}
__device__ __forceinline__ void mma16816(float* c, const uint32_t* a, const uint32_t* b) {
    asm volatile(
        "mma.sync.aligned.m16n8k16.row.col.f32.bf16.bf16.f32 "
        "{%0,%1,%2,%3}, {%4,%5,%6,%7}, {%8,%9}, {%0,%1,%2,%3};"
        : "+f"(c[0]), "+f"(c[1]), "+f"(c[2]), "+f"(c[3])
        : "r"(a[0]), "r"(a[1]), "r"(a[2]), "r"(a[3]), "r"(b[0]), "r"(b[1]));
}

#define ROWP 40   // padded row length in bf16 elements (32 data + 8 pad)

// ================= generic tensor GEMM (conv / mp layers) ====================
template<int BN>
__global__ void __launch_bounds__(256, 2)
gemm_bf16x3_kernel(const float* __restrict__ A, const float* __restrict__ Bt,
                   const float* __restrict__ bias, float* __restrict__ C,
                   int ldc, int relu) {
    constexpr int WN = BN / 4;
    constexpr int NF = WN / 8;
    constexpr int NG = WN / 16;

    __shared__ __nv_bfloat16 Ah[128 * ROWP], Al[128 * ROWP];
    __shared__ __nv_bfloat16 Bh[BN * ROWP],  Bl[BN * ROWP];

    int tid = threadIdx.x, lane = tid & 31, wid = tid >> 5;
    int wm = wid >> 2, wn = wid & 3;
    int bn = blockIdx.x * BN;
    int bm = blockIdx.y * 128;

    float acc[4][NF][4];
#pragma unroll
    for (int mt = 0; mt < 4; mt++)
#pragma unroll
        for (int nf = 0; nf < NF; nf++)
#pragma unroll
            for (int j = 0; j < 4; j++) acc[mt][nf][j] = 0.0f;

    int t8 = lane >> 3, lr = lane & 7;
    int atm = lr + 8 * (t8 & 1), atk0 = (t8 >> 1) * 8;
    int btn = lr + 8 * (t8 >> 1), btk0 = (t8 & 1) * 8;

    for (int kc = 0; kc < 4; kc++) {
#pragma unroll
        for (int i = 0; i < 4; i++) {
            int idx = tid + i * 256;
            int r = idx >> 3, c4 = idx & 7;
            float4 v = *(const float4*)&A[(size_t)(bm + r) * HDIM + kc * 32 + c4 * 4];
            __nv_bfloat162 h0 = __floats2bfloat162_rn(v.x, v.y);
            __nv_bfloat162 h1 = __floats2bfloat162_rn(v.z, v.w);
            __nv_bfloat162 l0 = __floats2bfloat162_rn(v.x - __low2float(h0),
                                                      v.y - __high2float(h0));
            __nv_bfloat162 l1 = __floats2bfloat162_rn(v.z - __low2float(h1),
                                                      v.w - __high2float(h1));
            int o = r * (ROWP / 2) + c4 * 2;
            ((__nv_bfloat162*)Ah)[o] = h0; ((__nv_bfloat162*)Ah)[o + 1] = h1;
            ((__nv_bfloat162*)Al)[o] = l0; ((__nv_bfloat162*)Al)[o + 1] = l1;
        }
#pragma unroll
        for (int i = 0; i < BN / 32; i++) {
            int idx = tid + i * 256;
            int r = idx >> 3, c4 = idx & 7;
            float4 v = *(const float4*)&Bt[(size_t)(bn + r) * HDIM + kc * 32 + c4 * 4];
            __nv_bfloat162 h0 = __floats2bfloat162_rn(v.x, v.y);
            __nv_bfloat162 h1 = __floats2bfloat162_rn(v.z, v.w);
            __nv_bfloat162 l0 = __floats2bfloat162_rn(v.x - __low2float(h0),
                                                      v.y - __high2float(h0));
            __nv_bfloat162 l1 = __floats2bfloat162_rn(v.z - __low2float(h1),
                                                      v.w - __high2float(h1));
            int o = r * (ROWP / 2) + c4 * 2;
            ((__nv_bfloat162*)Bh)[o] = h0; ((__nv_bfloat162*)Bh)[o + 1] = h1;
            ((__nv_bfloat162*)Bl)[o] = l0; ((__nv_bfloat162*)Bl)[o + 1] = l1;
        }
        __syncthreads();

#pragma unroll
        for (int ks = 0; ks < 2; ks++) {
            uint32_t afh[4][4], afl[4][4], bfh[NG][4], bfl[NG][4];
            int ak = ks * 16 + atk0;
            int bk = ks * 16 + btk0;
#pragma unroll
            for (int mt = 0; mt < 4; mt++) {
                int row = wm * 64 + mt * 16 + atm;
                ldsm4(afh[mt], &Ah[row * ROWP + ak]);
                ldsm4(afl[mt], &Al[row * ROWP + ak]);
            }
#pragma unroll
            for (int ng = 0; ng < NG; ng++) {
                int row = wn * WN + ng * 16 + btn;
                ldsm4(bfh[ng], &Bh[row * ROWP + bk]);
                ldsm4(bfl[ng], &Bl[row * ROWP + bk]);
            }
#pragma unroll
            for (int mt = 0; mt < 4; mt++)
#pragma unroll
                for (int nf = 0; nf < NF; nf++) {
                    const uint32_t* bh = &bfh[nf >> 1][2 * (nf & 1)];
                    const uint32_t* bl = &bfl[nf >> 1][2 * (nf & 1)];
                    mma16816(acc[mt][nf], afh[mt], bh);
                    mma16816(acc[mt][nf], afh[mt], bl);
                    mma16816(acc[mt][nf], afl[mt], bh);
                }
        }
        __syncthreads();
    }

#pragma unroll
    for (int mt = 0; mt < 4; mt++) {
        int r0 = bm + wm * 64 + mt * 16 + (lane >> 2);
#pragma unroll
        for (int nf = 0; nf < NF; nf++) {
            int col = bn + wn * WN + nf * 8 + 2 * (lane & 3);
            float b0 = bias ? bias[col] : 0.0f;
            float b1 = bias ? bias[col + 1] : 0.0f;
            float v0 = acc[mt][nf][0] + b0, v1 = acc[mt][nf][1] + b1;
            float v2 = acc[mt][nf][2] + b0, v3 = acc[mt][nf][3] + b1;
            if (relu) {
                v0 = fmaxf(v0, 0.f); v1 = fmaxf(v1, 0.f);
                v2 = fmaxf(v2, 0.f); v3 = fmaxf(v3, 0.f);
            }
            *(float2*)&C[(size_t)r0 * ldc + col]       = make_float2(v0, v1);
            *(float2*)&C[(size_t)(r0 + 8) * ldc + col] = make_float2(v2, v3);
        }
    }
}

// ================= fused GRU: gi-GEMM + gh-GEMM + elementwise ================
#define FSM_AAGG_H 0
#define FSM_AAGG_L (64 * ROWP)
#define FSM_AX_H   (2 * 64 * ROWP)
#define FSM_AX_L   (3 * 64 * ROWP)
#define FSM_BI_H   (4 * 64 * ROWP)
#define FSM_BI_L   (4 * 64 * ROWP + 128 * ROWP)
#define FSM_BH_H   (4 * 64 * ROWP + 2 * 128 * ROWP)
#define FSM_BH_L   (4 * 64 * ROWP + 3 * 128 * ROWP)
#define FSM_TOTAL  ((4 * 64 * ROWP + 4 * 128 * ROWP) * 2)   // bytes = 61440

__global__ void __launch_bounds__(256, 1)
gru_fused_kernel(const float* __restrict__ agg,
                 const __nv_bfloat16* __restrict__ wih, const __nv_bfloat16* __restrict__ wil,
                 const __nv_bfloat16* __restrict__ whh, const __nv_bfloat16* __restrict__ whl,
                 const float* __restrict__ bi, const float* __restrict__ bh,
                 float* __restrict__ x) {
    extern __shared__ __align__(16) char fsm[];
    __nv_bfloat16* AaggH = (__nv_bfloat16*)fsm + FSM_AAGG_H;
    __nv_bfloat16* AaggL = (__nv_bfloat16*)fsm + FSM_AAGG_L;
    __nv_bfloat16* AxH   = (__nv_bfloat16*)fsm + FSM_AX_H;
    __nv_bfloat16* AxL   = (__nv_bfloat16*)fsm + FSM_AX_L;
    __nv_bfloat16* BiH   = (__nv_bfloat16*)fsm + FSM_BI_H;
    __nv_bfloat16* BiL   = (__nv_bfloat16*)fsm + FSM_BI_L;
    __nv_bfloat16* BhH   = (__nv_bfloat16*)fsm + FSM_BH_H;
    __nv_bfloat16* BhL   = (__nv_bfloat16*)fsm + FSM_BH_L;

    int tid = threadIdx.x, lane = tid & 31, wid = tid >> 5;
    int wm = wid >> 2, wn = wid & 3;     // 2m x 4n
    int bm = blockIdx.x * 64;

    float a_r[2][4][4], a_z[2][4][4], a_i[2][4][4], a_h[2][4][4];
#pragma unroll
    for (int mt = 0; mt < 2; mt++)
#pragma unroll
        for (int nf = 0; nf < 4; nf++)
#pragma unroll
            for (int j = 0; j < 4; j++) {
                a_r[mt][nf][j] = 0.f; a_z[mt][nf][j] = 0.f;
                a_i[mt][nf][j] = 0.f; a_h[mt][nf][j] = 0.f;
            }

    int t8 = lane >> 3, lr = lane & 7;
    int atm = lr + 8 * (t8 & 1), atk0 = (t8 >> 1) * 8;
    int btn = lr + 8 * (t8 >> 1), btk0 = (t8 & 1) * 8;

    for (int kc = 0; kc < 4; kc++) {
#pragma unroll
        for (int i = 0; i < 2; i++) {
            int idx = tid + i * 256;
            int r = idx >> 3, c4 = idx & 7;
            int o = r * (ROWP / 2) + c4 * 2;
            {
                float4 v = *(const float4*)&agg[(size_t)(bm + r) * HDIM + kc * 32 + c4 * 4];
                __nv_bfloat162 h0 = __floats2bfloat162_rn(v.x, v.y);
                __nv_bfloat162 h1 = __floats2bfloat162_rn(v.z, v.w);
                __nv_bfloat162 l0 = __floats2bfloat162_rn(v.x - __low2float(h0),
                                                          v.y - __high2float(h0));
                __nv_bfloat162 l1 = __floats2bfloat162_rn(v.z - __low2float(h1),
                                                          v.w - __high2float(h1));
                ((__nv_bfloat162*)AaggH)[o] = h0; ((__nv_bfloat162*)AaggH)[o + 1] = h1;
                ((__nv_bfloat162*)AaggL)[o] = l0; ((__nv_bfloat162*)AaggL)[o + 1] = l1;
            }
            {
                float4 v = *(const float4*)&x[(size_t)(bm + r) * HDIM + kc * 32 + c4 * 4];
                __nv_bfloat162 h0 = __floats2bfloat162_rn(v.x, v.y);
                __nv_bfloat162 h1 = __floats2bfloat162_rn(v.z, v.w);
                __nv_bfloat162 l0 = __floats2bfloat162_rn(v.x - __low2float(h0),
                                                          v.y - __high2float(h0));
                __nv_bfloat162 l1 = __floats2bfloat162_rn(v.z - __low2float(h1),
                                                          v.w - __high2float(h1));
                ((__nv_bfloat162*)AxH)[o] = h0; ((__nv_bfloat162*)AxH)[o + 1] = h1;
                ((__nv_bfloat162*)AxL)[o] = l0; ((__nv_bfloat162*)AxL)[o + 1] = l1;
            }
        }
        __syncthreads();

#pragma unroll
        for (int g = 0; g < 3; g++) {
#pragma unroll
            for (int i = 0; i < 2; i++) {
                int idx = tid + i * 256;
                int r = idx >> 2, c8 = idx & 3;
                size_t src = (size_t)(g * 128 + r) * HDIM + kc * 32 + c8 * 8;
                int dst = r * ROWP + c8 * 8;
                *(uint4*)&BiH[dst] = *(const uint4*)&wih[src];
                *(uint4*)&BiL[dst] = *(const uint4*)&wil[src];
                *(uint4*)&BhH[dst] = *(const uint4*)&whh[src];
                *(uint4*)&BhL[dst] = *(const uint4*)&whl[src];
            }
            __syncthreads();

#pragma unroll
            for (int ks = 0; ks < 2; ks++) {
                uint32_t agh[2][4], agl[2][4], axh[2][4], axl[2][4];
                uint32_t bih[2][4], bil[2][4], bhh2[2][4], bhl2[2][4];
                int ak = ks * 16 + atk0;
                int bk = ks * 16 + btk0;
#pragma unroll
                for (int mt = 0; mt < 2; mt++) {
                    int row = wm * 32 + mt * 16 + atm;
                    ldsm4(agh[mt], &AaggH[row * ROWP + ak]);
                    ldsm4(agl[mt], &AaggL[row * ROWP + ak]);
                    ldsm4(axh[mt], &AxH[row * ROWP + ak]);
                    ldsm4(axl[mt], &AxL[row * ROWP + ak]);
                }
#pragma unroll
                for (int ng = 0; ng < 2; ng++) {
                    int row = wn * 32 + ng * 16 + btn;
                    ldsm4(bih[ng],  &BiH[row * ROWP + bk]);
                    ldsm4(bil[ng],  &BiL[row * ROWP + bk]);
                    ldsm4(bhh2[ng], &BhH[row * ROWP + bk]);
                    ldsm4(bhl2[ng], &BhL[row * ROWP + bk]);
                }
#pragma unroll
                for (int mt = 0; mt < 2; mt++)
#pragma unroll
                    for (int nf = 0; nf < 4; nf++) {
                        const uint32_t* pih = &bih[nf >> 1][2 * (nf & 1)];
                        const uint32_t* pil = &bil[nf >> 1][2 * (nf & 1)];
                        const uint32_t* phh = &bhh2[nf >> 1][2 * (nf & 1)];
                        const uint32_t* phl = &bhl2[nf >> 1][2 * (nf & 1)];
                        if (g < 2) {
                            float* d = (g == 0) ? a_r[mt][nf] : a_z[mt][nf];
                            mma16816(d, agh[mt], pih);
                            mma16816(d, agh[mt], pil);
                            mma16816(d, agl[mt], pih);
                            mma16816(d, axh[mt], phh);
                            mma16816(d, axh[mt], phl);
                            mma16816(d, axl[mt], phh);
                        } else {
                            mma16816(a_i[mt][nf], agh[mt], pih);
                            mma16816(a_i[mt][nf], agh[mt], pil);
                            mma16816(a_i[mt][nf], agl[mt], pih);
                            mma16816(a_h[mt][nf], axh[mt], phh);
                            mma16816(a_h[mt][nf], axh[mt], phl);
                            mma16816(a_h[mt][nf], axl[mt], phh);
                        }
                    }
            }
            __syncthreads();
        }
    }

#pragma unroll
    for (int mt = 0; mt < 2; mt++) {
        int r0 = bm + wm * 32 + mt * 16 + (lane >> 2);
#pragma unroll
        for (int nf = 0; nf < 4; nf++) {
            int h = wn * 32 + nf * 8 + 2 * (lane & 3);
            float brz0 = bi[h] + bh[h],             brz1 = bi[h + 1] + bh[h + 1];
            float bzz0 = bi[128 + h] + bh[128 + h], bzz1 = bi[129 + h] + bh[129 + h];
            float bin0 = bi[256 + h], bin1 = bi[257 + h];
            float bhn0 = bh[256 + h], bhn1 = bh[257 + h];

            float2 x0 = *(const float2*)&x[(size_t)r0 * HDIM + h];
            float2 x1 = *(const float2*)&x[(size_t)(r0 + 8) * HDIM + h];

            float r00 = sigm(a_r[mt][nf][0] + brz0), r01 = sigm(a_r[mt][nf][1] + brz1);
            float r10 = sigm(a_r[mt][nf][2] + brz0), r11 = sigm(a_r[mt][nf][3] + brz1);
            float z00 = sigm(a_z[mt][nf][0] + bzz0), z01 = sigm(a_z[mt][nf][1] + bzz1);
            float z10 = sigm(a_z[mt][nf][2] + bzz0), z11 = sigm(a_z[mt][nf][3] + bzz1);
            float n00 = tanhf(a_i[mt][nf][0] + bin0 + r00 * (a_h[mt][nf][0] + bhn0));
            float n01 = tanhf(a_i[mt][nf][1] + bin1 + r01 * (a_h[mt][nf][1] + bhn1));
            float n10 = tanhf(a_i[mt][nf][2] + bin0 + r10 * (a_h[mt][nf][2] + bhn0));
            float n11 = tanhf(a_i[mt][nf][3] + bin1 + r11 * (a_h[mt][nf][3] + bhn1));

            float2 o0, o1;
            o0.x = (1.f - z00) * n00 + z00 * x0.x;
            o0.y = (1.f - z01) * n01 + z01 * x0.y;
            o1.x = (1.f - z10) * n10 + z10 * x1.x;
            o1.y = (1.f - z11) * n11 + z11 * x1.y;
            *(float2*)&x[(size_t)r0 * HDIM + h]       = o0;
            *(float2*)&x[(size_t)(r0 + 8) * HDIM + h] = o1;
        }
    }
}

// ---------------- fused readout: 2 dense layers + logits + softmax ----------------
#define NPB 16
__global__ void readout_kernel(const float* __restrict__ nm,
                               const float* __restrict__ W1, const float* __restrict__ b1,
                               const float* __restrict__ W2, const float* __restrict__ b2,
                               const float* __restrict__ W3, const float* __restrict__ b3,
                               float* __restrict__ out) {
    __shared__ float nms[64], h1s[128], h2s[128], red[128];
    __shared__ float l0sh;
    int t = threadIdx.x;   // 128
    int v0 = blockIdx.x * NPB;
    for (int v = v0; v < v0 + NPB; v++) {
        if (t < 64) nms[t] = nm[v * MDIM + t];
        __syncthreads();
        float a = b1[t];
#pragma unroll 4
        for (int k = 0; k < 64; k++) a += nms[k] * W1[k * 128 + t];
        h1s[t] = fmaxf(a, 0.f);
        __syncthreads();
        float c = b2[t];
#pragma unroll 4
        for (int k = 0; k < 128; k++) c += h1s[k] * W2[k * 128 + t];
        h2s[t] = fmaxf(c, 0.f);
        __syncthreads();
        red[t] = h2s[t] * W3[2 * t + 0];
        __syncthreads();
        for (int s = 64; s > 0; s >>= 1) {
            if (t < s) red[t] += red[t + s];
            __syncthreads();
        }
        if (t == 0) l0sh = red[0] + b3[0];
        __syncthreads();
        red[t] = h2s[t] * W3[2 * t + 1];
        __syncthreads();
        for (int s = 64; s > 0; s >>= 1) {
            if (t < s) red[t] += red[t + s];
            __syncthreads();
        }
        if (t == 0) {
            float l0 = l0sh;
            float l1 = red[0] + b3[1];
            float mx = fmaxf(l0, l1);
            float e0 = expf(l0 - mx), e1 = expf(l1 - mx);
            float s_ = e0 + e1;
            out[v * 2 + 0] = e0 / s_;
            out[v * 2 + 1] = e1 / s_;
        }
        __syncthreads();
    }
}

// ---------------- launch ----------------
extern "C" void kernel_launch(void* const* d_in, const int* in_sizes, int n_in,
                              void* d_out, int out_size) {
    const float* jvals = (const float*)d_in[0];
    // d_in[1] = b (unused: only defines n_nodes)
    const int* row = (const int*)d_in[2];
    const int* col = (const int*)d_in[3];
    const float* convW  = (const float*)d_in[4];
    const float* gru_wi = (const float*)d_in[5];
    const float* gru_wh = (const float*)d_in[6];
    const float* gru_bi = (const float*)d_in[7];
    const float* gru_bh = (const float*)d_in[8];
    const float* mp_W1 = (const float*)d_in[9];
    const float* mp_b1 = (const float*)d_in[10];
    const float* mp_W2 = (const float*)d_in[11];
    const float* mp_b2 = (const float*)d_in[12];
    const float* mp_W3 = (const float*)d_in[13];
    const float* mp_b3 = (const float*)d_in[14];
    const float* ro_W1 = (const float*)d_in[15];
    const float* ro_b1 = (const float*)d_in[16];
    const float* ro_W2 = (const float*)d_in[17];
    const float* ro_b2 = (const float*)d_in[18];
    const float* ro_W3 = (const float*)d_in[19];
    const float* ro_b3 = (const float*)d_in[20];
    float* out = (float*)d_out;

    float *x, *m, *agg, *gi, *nm, *wt, *u0, *u1, *v0, *v1;
    __nv_bfloat16 *wih, *wil, *whh, *whl;
    int *degv, *offv, *curv, *lstv, *degr, *offr, *curr, *lstr;
    cudaGetSymbolAddress((void**)&x,   g_x);
    cudaGetSymbolAddress((void**)&m,   g_m);
    cudaGetSymbolAddress((void**)&agg, g_agg);
    cudaGetSymbolAddress((void**)&gi,  g_gi);
    cudaGetSymbolAddress((void**)&nm,  g_nm);
    cudaGetSymbolAddress((void**)&wt,  g_wt);
    cudaGetSymbolAddress((void**)&u0,  g_u0);
    cudaGetSymbolAddress((void**)&u1,  g_u1);
    cudaGetSymbolAddress((void**)&v0,  g_v0);
    cudaGetSymbolAddress((void**)&v1,  g_v1);
    cudaGetSymbolAddress((void**)&wih, g_wih);
    cudaGetSymbolAddress((void**)&wil, g_wil);
    cudaGetSymbolAddress((void**)&whh, g_whh);
    cudaGetSymbolAddress((void**)&whl, g_whl);
    cudaGetSymbolAddress((void**)&degv, g_deg_var);
    cudaGetSymbolAddress((void**)&offv, g_off_var);
    cudaGetSymbolAddress((void**)&curv, g_cur_var);
    cudaGetSymbolAddress((void**)&lstv, g_lst_var);
    cudaGetSymbolAddress((void**)&degr, g_deg_row);
    cudaGetSymbolAddress((void**)&offr, g_off_row);
    cudaGetSymbolAddress((void**)&curr, g_cur_row);
    cudaGetSymbolAddress((void**)&lstr, g_lst_row);

    float* wt_conv1 = wt;
    float* wt_mp1   = wt + 16384;
    float* wt_mp2   = wt + 32768;
    float* wt_mp3   = wt + 49152;

    cudaFuncSetAttribute(gru_fused_kernel,
                         cudaFuncAttributeMaxDynamicSharedMemorySize, FSM_TOTAL);

    // ---- CSR build ----
    zero_deg_kernel<<<NNODE / 256, 256>>>(degv, degr);
    count_kernel<<<NEDGE / 256, 256>>>(row, col, degv, degr);
    scan_kernel<<<1, 1024>>>(degv, offv);
    scan_kernel<<<1, 1024>>>(degr, offr);
    copy_cur_kernel<<<NNODE / 256, 256>>>(offv, curv, offr, curr);
    scatter_kernel<<<NEDGE / 256, 256>>>(row, col, curv, lstv, curr, lstr);

    // ---- weight prep ----
    transpose_kernel<<<(128 * 128) / 256, 256>>>(convW + 16384, wt_conv1, 128, 128);
    transpose_kernel<<<(128 * 128) / 256, 256>>>(mp_W1,         wt_mp1,   128, 128);
    transpose_kernel<<<(128 * 128) / 256, 256>>>(mp_W2,         wt_mp2,   128, 128);
    transpose_kernel<<<(128 * 64) / 256, 256>>>(mp_W3,          wt_mp3,   128, 64);
    split_w_kernel<<<(H3 * HDIM) / 256, 256>>>(gru_wi, wih, wil, H3 * HDIM);
    split_w_kernel<<<(H3 * HDIM) / 256, 256>>>(gru_wh, whh, whl, H3 * HDIM);
    prep_l0_kernel<<<3, 128>>>(convW, gru_wi, gru_wh, u0, u1, v0, v1);

    // ---- layer 0: fully elementwise (x rank-2 sparse), exact fp32 ----
    layer0_kernel<<<NTOT / L0_NPB, 128>>>(jvals, offv, lstv, u0, u1, v0, v1,
                                          gru_bi, gru_bh, x);

    // ---- layer 1: full path ----
    gemm_bf16x3_kernel<128><<<dim3(1, NTOT / 128), 256>>>(
        x, wt_conv1, nullptr, m, 128, 0);
    factor_agg_kernel<<<(NEDGE * 32) / 128, 128>>>(m, row, col, agg);
    var_agg_kernel<<<NNODE, 128>>>(m, offv, lstv, agg);
    gru_fused_kernel<<<NTOT / 64, 256, FSM_TOTAL>>>(
        agg, wih, wil, whh, whl, gru_bi, gru_bh, x);

    // ---- edge MLP on factor rows ----
    const float* xf = x + (size_t)NNODE * HDIM;
    gemm_bf16x3_kernel<128><<<dim3(1, NEDGE / 128), 256>>>(
        xf, wt_mp1, mp_b1, m, 128, 1);
    gemm_bf16x3_kernel<128><<<dim3(1, NEDGE / 128), 256>>>(
        m, wt_mp2, mp_b2, agg, 128, 1);
    gemm_bf16x3_kernel<64><<<dim3(1, NEDGE / 128), 256>>>(
        agg, wt_mp3, mp_b3, gi, 64, 0);

    // ---- node_msgs = segment_sum(msgs, row) ----
    node_msgs_kernel<<<NNODE, 64>>>(gi, offr, lstr, nm);

    // ---- readout + softmax ----
    readout_kernel<<<NNODE / NPB, 128>>>(nm, ro_W1, ro_b1, ro_W2, ro_b2, ro_W3, ro_b3, out);
}